// round 1
// baseline (speedup 1.0000x reference)
#include <cuda_runtime.h>
#include <cstdint>

// Problem constants
#define BATCH 4
#define SEQ   2048
#define CH    1024
#define NHEAD 16
#define HD    64
#define C3    (3*CH)

// Scratch (no cudaMalloc allowed): qkv [B,T,3C], attn out [B,T,C]
__device__ float g_qkv[(size_t)BATCH * SEQ * C3];   // 96 MB
__device__ float g_att[(size_t)BATCH * SEQ * CH];   // 32 MB

// ---------------------------------------------------------------------------
// GEMM: C[m,n] = sum_k A[m,k] * B[n,k] + bias[n]
// A: MxK row-major, B: NxK row-major (torch Linear weight), C: MxN row-major
// 128x128 block tile, BK=16, 256 threads, 8x8 per-thread register tile.
// ---------------------------------------------------------------------------
#define BM 128
#define BN 128
#define BKK 16

__global__ __launch_bounds__(256) void gemm_tn_bias(
    const float* __restrict__ A, const float* __restrict__ B,
    const float* __restrict__ bias, float* __restrict__ C,
    int M, int N, int K)
{
    __shared__ float As[BKK][BM];
    __shared__ float Bs[BKK][BN];

    const int tid = threadIdx.x;
    const int m0 = blockIdx.y * BM;
    const int n0 = blockIdx.x * BN;
    const int tx = tid & 15;        // 0..15
    const int ty = tid >> 4;        // 0..15

    float acc[8][8];
    #pragma unroll
    for (int i = 0; i < 8; ++i)
        #pragma unroll
        for (int j = 0; j < 8; ++j) acc[i][j] = 0.f;

    // loader mapping: each thread loads 2 float4 of A and 2 float4 of B per k-tile
    const int lr = tid >> 2;            // 0..63
    const int lc = (tid & 3) * 4;       // 0,4,8,12
    const float* Aptr = A + (size_t)(m0 + lr) * K + lc;
    const float* Bptr = B + (size_t)(n0 + lr) * K + lc;

    for (int k0 = 0; k0 < K; k0 += BKK) {
        #pragma unroll
        for (int r = 0; r < 2; ++r) {
            float4 a = *(const float4*)(Aptr + (size_t)r * 64 * K + k0);
            As[lc + 0][lr + r * 64] = a.x;
            As[lc + 1][lr + r * 64] = a.y;
            As[lc + 2][lr + r * 64] = a.z;
            As[lc + 3][lr + r * 64] = a.w;
            float4 b = *(const float4*)(Bptr + (size_t)r * 64 * K + k0);
            Bs[lc + 0][lr + r * 64] = b.x;
            Bs[lc + 1][lr + r * 64] = b.y;
            Bs[lc + 2][lr + r * 64] = b.z;
            Bs[lc + 3][lr + r * 64] = b.w;
        }
        __syncthreads();

        #pragma unroll
        for (int kk = 0; kk < BKK; ++kk) {
            float a_frag[8], b_frag[8];
            #pragma unroll
            for (int i = 0; i < 4; ++i) {
                ((float4*)a_frag)[0] = *(const float4*)(&As[kk][ty * 8]);
                ((float4*)a_frag)[1] = *(const float4*)(&As[kk][ty * 8 + 4]);
                ((float4*)b_frag)[0] = *(const float4*)(&Bs[kk][tx * 8]);
                ((float4*)b_frag)[1] = *(const float4*)(&Bs[kk][tx * 8 + 4]);
                break;
            }
            #pragma unroll
            for (int i = 0; i < 8; ++i)
                #pragma unroll
                for (int j = 0; j < 8; ++j)
                    acc[i][j] += a_frag[i] * b_frag[j];
        }
        __syncthreads();
    }

    // epilogue: add bias, vectorized stores
    float bfr[8];
    #pragma unroll
    for (int j = 0; j < 8; j += 4) {
        float4 bb = *(const float4*)(bias + n0 + tx * 8 + j);
        bfr[j + 0] = bb.x; bfr[j + 1] = bb.y; bfr[j + 2] = bb.z; bfr[j + 3] = bb.w;
    }
    #pragma unroll
    for (int i = 0; i < 8; ++i) {
        const int m = m0 + ty * 8 + i;
        float4 v0, v1;
        v0.x = acc[i][0] + bfr[0]; v0.y = acc[i][1] + bfr[1];
        v0.z = acc[i][2] + bfr[2]; v0.w = acc[i][3] + bfr[3];
        v1.x = acc[i][4] + bfr[4]; v1.y = acc[i][5] + bfr[5];
        v1.z = acc[i][6] + bfr[6]; v1.w = acc[i][7] + bfr[7];
        *(float4*)(C + (size_t)m * N + n0 + tx * 8)     = v0;
        *(float4*)(C + (size_t)m * N + n0 + tx * 8 + 4) = v1;
    }
}

// ---------------------------------------------------------------------------
// Causal flash attention, fp32 SIMT.
// Block = one (batch, head, 128-row q tile); 128 threads, 1 q row per thread.
// q and accumulator live in registers; K/V tiles (64x64) in shared memory.
// qkv layout: [B, T, 3C], q at col h*64, k at C + h*64, v at 2C + h*64.
// ---------------------------------------------------------------------------
#define QTILE 128
#define KTILE 64

__global__ __launch_bounds__(128) void flash_attn_causal(
    const float* __restrict__ qkv, float* __restrict__ out)
{
    __shared__ float Ks[KTILE][HD];
    __shared__ float Vs[KTILE][HD];

    const int tid = threadIdx.x;
    const int h = blockIdx.y;
    const int b = blockIdx.z;
    const int qrow = blockIdx.x * QTILE + tid;

    // load q into registers
    const float* qptr = qkv + ((size_t)b * SEQ + qrow) * C3 + h * HD;
    float q[HD];
    #pragma unroll
    for (int d = 0; d < HD; d += 4) {
        float4 t = *(const float4*)(qptr + d);
        q[d + 0] = t.x; q[d + 1] = t.y; q[d + 2] = t.z; q[d + 3] = t.w;
    }

    float acc[HD];
    #pragma unroll
    for (int d = 0; d < HD; ++d) acc[d] = 0.f;
    float mx = -1e30f;
    float l = 0.f;

    const int kend = blockIdx.x * QTILE + QTILE;   // exclusive upper bound on keys this block needs
    for (int j0 = 0; j0 < kend; j0 += KTILE) {
        // cooperative K/V tile load: 64 rows x 64 cols each, float4 vectorized
        const float* kbase = qkv + ((size_t)b * SEQ + j0) * C3 + CH + h * HD;
        const float* vbase = kbase + CH;
        #pragma unroll
        for (int i = 0; i < 8; ++i) {
            const int idx = tid + i * 128;
            const int r = idx >> 4;          // 0..63
            const int c = (idx & 15) * 4;    // 0..60
            *(float4*)(&Ks[r][c]) = *(const float4*)(kbase + (size_t)r * C3 + c);
            *(float4*)(&Vs[r][c]) = *(const float4*)(vbase + (size_t)r * C3 + c);
        }
        __syncthreads();

        const int jmax = min(KTILE, qrow - j0 + 1);   // # valid keys for this thread in tile
        for (int j = 0; j < jmax; ++j) {
            float s = 0.f;
            #pragma unroll
            for (int d = 0; d < HD; ++d) s += q[d] * Ks[j][d];
            s *= 0.125f;  // 1/sqrt(64)

            if (s <= mx) {
                const float p = __expf(s - mx);
                l += p;
                #pragma unroll
                for (int d = 0; d < HD; ++d) acc[d] += p * Vs[j][d];
            } else {
                const float corr = __expf(mx - s);
                mx = s;
                l = l * corr + 1.f;
                #pragma unroll
                for (int d = 0; d < HD; ++d) acc[d] = acc[d] * corr + Vs[j][d];
            }
        }
        __syncthreads();
    }

    const float inv = 1.f / l;
    float* optr = out + ((size_t)b * SEQ + qrow) * CH + h * HD;
    #pragma unroll
    for (int d = 0; d < HD; d += 4) {
        float4 t;
        t.x = acc[d + 0] * inv; t.y = acc[d + 1] * inv;
        t.z = acc[d + 2] * inv; t.w = acc[d + 3] * inv;
        *(float4*)(optr + d) = t;
    }
}

// ---------------------------------------------------------------------------
extern "C" void kernel_launch(void* const* d_in, const int* in_sizes, int n_in,
                              void* d_out, int out_size)
{
    const float* x      = (const float*)d_in[0];  // [B,T,C]
    const float* W_attn = (const float*)d_in[1];  // [3C,C]
    const float* b_attn = (const float*)d_in[2];  // [3C]
    const float* W_proj = (const float*)d_in[3];  // [C,C]
    const float* b_proj = (const float*)d_in[4];  // [C]
    float* out = (float*)d_out;                   // [B,T,C]

    float* qkv; cudaGetSymbolAddress((void**)&qkv, g_qkv);
    float* att; cudaGetSymbolAddress((void**)&att, g_att);

    const int M = BATCH * SEQ;  // 8192

    // 1) QKV projection: [8192,1024] x [3072,1024]^T -> [8192,3072]
    {
        dim3 grid(C3 / BN, M / BM);
        gemm_tn_bias<<<grid, 256>>>(x, W_attn, b_attn, qkv, M, C3, CH);
    }
    // 2) causal flash attention -> g_att [8192,1024]
    {
        dim3 grid(SEQ / QTILE, NHEAD, BATCH);
        flash_attn_causal<<<grid, 128>>>(qkv, att);
    }
    // 3) output projection: [8192,1024] x [1024,1024]^T -> [8192,1024]
    {
        dim3 grid(CH / BN, M / BM);
        gemm_tn_bias<<<grid, 256>>>(att, W_proj, b_proj, out, M, CH, CH);
    }
}

// round 3
// speedup vs baseline: 1.5019x; 1.5019x over previous
#include <cuda_runtime.h>
#include <cstdint>

// Problem constants
#define BATCH 4
#define SEQ   2048
#define CH    1024
#define NHEAD 16
#define HD    64
#define C3    (3*CH)

// Scratch (no cudaMalloc allowed): qkv [B,T,3C], attn out [B,T,C]
__device__ float g_qkv[(size_t)BATCH * SEQ * C3];   // 96 MB
__device__ float g_att[(size_t)BATCH * SEQ * CH];   // 32 MB

// ===========================================================================
// mma.sync tf32 GEMM: C[m,n] = sum_k A[m,k]*B[n,k] + bias[n]
// A: MxK row-major; B: NxK row-major (torch Linear weight). K = 1024.
// CTA tile 128x128, BK=32, 256 threads (8 warps, 2x4), warp tile 64x32.
// cp.async double-buffered smem (fp32 staged, cvt.rna.tf32 after LDS).
// ===========================================================================
#define GK   1024
#define BM   128
#define BN   128
#define BK   32
#define KTILES (GK/BK)          // 32
#define SA   36                  // padded row stride (floats) -> conflict-free frag LDS
#define ASZ  (BM*SA)             // floats per A stage
#define BSZ  (BN*SA)
#define STAGEF (ASZ+BSZ)         // floats per stage
#define GEMM_SMEM_BYTES (2*STAGEF*4)   // 73728 B

__device__ __forceinline__ uint32_t smem_u32(const void* p) {
    uint32_t a;
    asm("{ .reg .u64 t; cvta.to.shared.u64 t, %1; cvt.u32.u64 %0, t; }" : "=r"(a) : "l"(p));
    return a;
}

__device__ __forceinline__ void cp_async16(uint32_t smem_addr, const void* gptr) {
    asm volatile("cp.async.cg.shared.global [%0], [%1], 16;" :: "r"(smem_addr), "l"(gptr));
}
#define CP_ASYNC_COMMIT() asm volatile("cp.async.commit_group;" ::: "memory")
#define CP_ASYNC_WAIT(n)  asm volatile("cp.async.wait_group %0;" :: "n"(n) : "memory")

__device__ __forceinline__ uint32_t f2tf32(float f) {
    uint32_t r;
    asm("cvt.rna.tf32.f32 %0, %1;" : "=r"(r) : "f"(f));
    return r;
}

__device__ __forceinline__ void mma_tf32(float* c,
    uint32_t a0, uint32_t a1, uint32_t a2, uint32_t a3, uint32_t b0, uint32_t b1)
{
    asm volatile(
        "mma.sync.aligned.m16n8k8.row.col.f32.tf32.tf32.f32 "
        "{%0,%1,%2,%3}, {%4,%5,%6,%7}, {%8,%9}, {%0,%1,%2,%3};"
        : "+f"(c[0]), "+f"(c[1]), "+f"(c[2]), "+f"(c[3])
        : "r"(a0), "r"(a1), "r"(a2), "r"(a3), "r"(b0), "r"(b1));
}

__global__ __launch_bounds__(256, 2) void gemm_mma_tf32(
    const float* __restrict__ A, const float* __restrict__ B,
    const float* __restrict__ bias, float* __restrict__ C,
    int M, int N)
{
    extern __shared__ float smem[];
    float* Abuf[2] = { smem,          smem + STAGEF };
    float* Bbuf[2] = { smem + ASZ,    smem + STAGEF + ASZ };
    const uint32_t sbase = smem_u32(smem);

    const int tid  = threadIdx.x;
    const int wid  = tid >> 5;
    const int lane = tid & 31;
    const int wm   = wid & 1;       // 0..1 -> 64-row slab
    const int wn   = wid >> 1;      // 0..3 -> 32-col slab
    const int lq   = lane >> 2;     // 0..7
    const int kq   = lane & 3;      // 0..3
    const int m0 = blockIdx.y * BM;
    const int n0 = blockIdx.x * BN;

    // global load mapping: 4 float4 per thread per matrix per stage
    // lin = tid + i*256; row = lin>>3 (0..127), col4 = lin&7 -> col = col4*4
    const int lrow = tid >> 3;
    const int lcol = (tid & 7) * 4;
    const float* Ag = A + (size_t)(m0 + lrow) * GK + lcol;
    const float* Bg = B + (size_t)(n0 + lrow) * GK + lcol;
    // smem store offsets (byte addresses)
    uint32_t sAaddr[2], sBaddr[2];
    #pragma unroll
    for (int s = 0; s < 2; ++s) {
        sAaddr[s] = sbase + (uint32_t)((Abuf[s] - smem) + lrow * SA + lcol) * 4u;
        sBaddr[s] = sbase + (uint32_t)((Bbuf[s] - smem) + lrow * SA + lcol) * 4u;
    }

    float c[4][4][4];
    #pragma unroll
    for (int i = 0; i < 4; ++i)
        #pragma unroll
        for (int j = 0; j < 4; ++j)
            #pragma unroll
            for (int r = 0; r < 4; ++r) c[i][j][r] = 0.f;

    // prologue: stage 0
    #pragma unroll
    for (int i = 0; i < 4; ++i) {
        const int rs = i * 32;   // 4 groups of 32 rows (since 256 thr cover 32 rows per pass? no:
        // actually each i covers rows via lin = tid + i*256 -> row += 32 per i
        cp_async16(sAaddr[0] + (uint32_t)(rs * SA) * 4u, Ag + (size_t)rs * GK);
        cp_async16(sBaddr[0] + (uint32_t)(rs * SA) * 4u, Bg + (size_t)rs * GK);
    }
    CP_ASYNC_COMMIT();

    // per-thread fragment LDS base offsets (float indices, within a stage's A/B)
    const int aoff = (wm * 64 + lq) * SA + kq;
    const int boff = (wn * 32 + lq) * SA + kq;

    for (int kt = 0; kt < KTILES; ++kt) {
        const int buf = kt & 1;
        if (kt + 1 < KTILES) {
            const int nb = (kt + 1) & 1;
            const int k0 = (kt + 1) * BK;
            #pragma unroll
            for (int i = 0; i < 4; ++i) {
                const int rs = i * 32;
                cp_async16(sAaddr[nb] + (uint32_t)(rs * SA) * 4u, Ag + (size_t)rs * GK + k0);
                cp_async16(sBaddr[nb] + (uint32_t)(rs * SA) * 4u, Bg + (size_t)rs * GK + k0);
            }
            CP_ASYNC_COMMIT();
            CP_ASYNC_WAIT(1);
        } else {
            CP_ASYNC_WAIT(0);
        }
        __syncthreads();

        const float* As = Abuf[buf];
        const float* Bs = Bbuf[buf];
        #pragma unroll
        for (int ks = 0; ks < 4; ++ks) {
            const int kk = ks * 8;
            uint32_t a[4][4], b[4][2];
            #pragma unroll
            for (int mf = 0; mf < 4; ++mf) {
                const int base = aoff + mf * 16 * SA + kk;
                a[mf][0] = f2tf32(As[base]);
                a[mf][1] = f2tf32(As[base + 8 * SA]);
                a[mf][2] = f2tf32(As[base + 4]);
                a[mf][3] = f2tf32(As[base + 8 * SA + 4]);
            }
            #pragma unroll
            for (int nf = 0; nf < 4; ++nf) {
                const int base = boff + nf * 8 * SA + kk;
                b[nf][0] = f2tf32(Bs[base]);
                b[nf][1] = f2tf32(Bs[base + 4]);
            }
            #pragma unroll
            for (int mf = 0; mf < 4; ++mf)
                #pragma unroll
                for (int nf = 0; nf < 4; ++nf)
                    mma_tf32(c[mf][nf], a[mf][0], a[mf][1], a[mf][2], a[mf][3],
                             b[nf][0], b[nf][1]);
        }
        __syncthreads();
    }

    // epilogue: c0/c1 at (row, col..col+1), c2/c3 at (row+8, col..col+1)
    const int crow = m0 + wm * 64 + lq;
    const int ccol = n0 + wn * 32 + (lane & 3) * 2;
    #pragma unroll
    for (int nf = 0; nf < 4; ++nf) {
        const int col = ccol + nf * 8;
        const float2 bb = *(const float2*)(bias + col);
        #pragma unroll
        for (int mf = 0; mf < 4; ++mf) {
            const int row = crow + mf * 16;
            float2 v0, v1;
            v0.x = c[mf][nf][0] + bb.x; v0.y = c[mf][nf][1] + bb.y;
            v1.x = c[mf][nf][2] + bb.x; v1.y = c[mf][nf][3] + bb.y;
            *(float2*)(C + (size_t)row * N + col)       = v0;
            *(float2*)(C + (size_t)(row + 8) * N + col) = v1;
        }
    }
}

// ---------------------------------------------------------------------------
// Causal flash attention, fp32 SIMT (unchanged, known-correct).
// ---------------------------------------------------------------------------
#define QTILE 128
#define KTILE 64

__global__ __launch_bounds__(128) void flash_attn_causal(
    const float* __restrict__ qkv, float* __restrict__ out)
{
    __shared__ float Ks[KTILE][HD];
    __shared__ float Vs[KTILE][HD];

    const int tid = threadIdx.x;
    const int h = blockIdx.y;
    const int b = blockIdx.z;
    const int qrow = blockIdx.x * QTILE + tid;

    const float* qptr = qkv + ((size_t)b * SEQ + qrow) * C3 + h * HD;
    float q[HD];
    #pragma unroll
    for (int d = 0; d < HD; d += 4) {
        float4 t = *(const float4*)(qptr + d);
        q[d + 0] = t.x; q[d + 1] = t.y; q[d + 2] = t.z; q[d + 3] = t.w;
    }

    float acc[HD];
    #pragma unroll
    for (int d = 0; d < HD; ++d) acc[d] = 0.f;
    float mx = -1e30f;
    float l = 0.f;

    const int kend = blockIdx.x * QTILE + QTILE;
    for (int j0 = 0; j0 < kend; j0 += KTILE) {
        const float* kbase = qkv + ((size_t)b * SEQ + j0) * C3 + CH + h * HD;
        const float* vbase = kbase + CH;
        #pragma unroll
        for (int i = 0; i < 8; ++i) {
            const int idx = tid + i * 128;
            const int r = idx >> 4;
            const int cc = (idx & 15) * 4;
            *(float4*)(&Ks[r][cc]) = *(const float4*)(kbase + (size_t)r * C3 + cc);
            *(float4*)(&Vs[r][cc]) = *(const float4*)(vbase + (size_t)r * C3 + cc);
        }
        __syncthreads();

        const int jmax = min(KTILE, qrow - j0 + 1);
        for (int j = 0; j < jmax; ++j) {
            float s = 0.f;
            #pragma unroll
            for (int d = 0; d < HD; ++d) s += q[d] * Ks[j][d];
            s *= 0.125f;

            if (s <= mx) {
                const float p = __expf(s - mx);
                l += p;
                #pragma unroll
                for (int d = 0; d < HD; ++d) acc[d] += p * Vs[j][d];
            } else {
                const float corr = __expf(mx - s);
                mx = s;
                l = l * corr + 1.f;
                #pragma unroll
                for (int d = 0; d < HD; ++d) acc[d] = acc[d] * corr + Vs[j][d];
            }
        }
        __syncthreads();
    }

    const float inv = 1.f / l;
    float* optr = out + ((size_t)b * SEQ + qrow) * CH + h * HD;
    #pragma unroll
    for (int d = 0; d < HD; d += 4) {
        float4 t;
        t.x = acc[d + 0] * inv; t.y = acc[d + 1] * inv;
        t.z = acc[d + 2] * inv; t.w = acc[d + 3] * inv;
        *(float4*)(optr + d) = t;
    }
}

// ---------------------------------------------------------------------------
extern "C" void kernel_launch(void* const* d_in, const int* in_sizes, int n_in,
                              void* d_out, int out_size)
{
    const float* x      = (const float*)d_in[0];  // [B,T,C]
    const float* W_attn = (const float*)d_in[1];  // [3C,C]
    const float* b_attn = (const float*)d_in[2];  // [3C]
    const float* W_proj = (const float*)d_in[3];  // [C,C]
    const float* b_proj = (const float*)d_in[4];  // [C]
    float* out = (float*)d_out;                   // [B,T,C]

    float* qkv; cudaGetSymbolAddress((void**)&qkv, g_qkv);
    float* att; cudaGetSymbolAddress((void**)&att, g_att);

    cudaFuncSetAttribute(gemm_mma_tf32,
                         cudaFuncAttributeMaxDynamicSharedMemorySize, GEMM_SMEM_BYTES);

    const int M = BATCH * SEQ;  // 8192

    // 1) QKV projection: [8192,1024] x [3072,1024]^T -> [8192,3072]
    {
        dim3 grid(C3 / BN, M / BM);
        gemm_mma_tf32<<<grid, 256, GEMM_SMEM_BYTES>>>(x, W_attn, b_attn, qkv, M, C3);
    }
    // 2) causal flash attention -> g_att [8192,1024]
    {
        dim3 grid(SEQ / QTILE, NHEAD, BATCH);
        flash_attn_causal<<<grid, 128>>>(qkv, att);
    }
    // 3) output projection: [8192,1024] x [1024,1024]^T -> [8192,1024]
    {
        dim3 grid(CH / BN, M / BM);
        gemm_mma_tf32<<<grid, 256, GEMM_SMEM_BYTES>>>(att, W_proj, b_proj, out, M, CH);
    }
}

// round 4
// speedup vs baseline: 3.0982x; 2.0628x over previous
#include <cuda_runtime.h>
#include <cstdint>

// Problem constants
#define BATCH 4
#define SEQ   2048
#define CH    1024
#define NHEAD 16
#define HD    64
#define C3    (3*CH)

// Scratch (no cudaMalloc allowed): qkv [B,T,3C], attn out [B,T,C]
__device__ float g_qkv[(size_t)BATCH * SEQ * C3];   // 96 MB
__device__ float g_att[(size_t)BATCH * SEQ * CH];   // 32 MB

// ===========================================================================
// Common mma helpers
// ===========================================================================
__device__ __forceinline__ uint32_t smem_u32(const void* p) {
    uint32_t a;
    asm("{ .reg .u64 t; cvta.to.shared.u64 t, %1; cvt.u32.u64 %0, t; }" : "=r"(a) : "l"(p));
    return a;
}

__device__ __forceinline__ void cp_async16(uint32_t smem_addr, const void* gptr) {
    asm volatile("cp.async.cg.shared.global [%0], [%1], 16;" :: "r"(smem_addr), "l"(gptr));
}
#define CP_ASYNC_COMMIT() asm volatile("cp.async.commit_group;" ::: "memory")
#define CP_ASYNC_WAIT(n)  asm volatile("cp.async.wait_group %0;" :: "n"(n) : "memory")

__device__ __forceinline__ uint32_t f2tf32(float f) {
    uint32_t r;
    asm("cvt.rna.tf32.f32 %0, %1;" : "=r"(r) : "f"(f));
    return r;
}
__device__ __forceinline__ float f2tf32f(float f) {
    return __uint_as_float(f2tf32(f));
}

__device__ __forceinline__ void mma_tf32(float* c,
    uint32_t a0, uint32_t a1, uint32_t a2, uint32_t a3, uint32_t b0, uint32_t b1)
{
    asm volatile(
        "mma.sync.aligned.m16n8k8.row.col.f32.tf32.tf32.f32 "
        "{%0,%1,%2,%3}, {%4,%5,%6,%7}, {%8,%9}, {%0,%1,%2,%3};"
        : "+f"(c[0]), "+f"(c[1]), "+f"(c[2]), "+f"(c[3])
        : "r"(a0), "r"(a1), "r"(a2), "r"(a3), "r"(b0), "r"(b1));
}

// ===========================================================================
// mma.sync tf32 GEMM (unchanged from round 3): C = A @ B^T + bias
// ===========================================================================
#define GK   1024
#define BM   128
#define BN   128
#define BK   32
#define KTILES (GK/BK)
#define SA   36
#define ASZ  (BM*SA)
#define BSZ  (BN*SA)
#define STAGEF (ASZ+BSZ)
#define GEMM_SMEM_BYTES (2*STAGEF*4)

__global__ __launch_bounds__(256, 2) void gemm_mma_tf32(
    const float* __restrict__ A, const float* __restrict__ B,
    const float* __restrict__ bias, float* __restrict__ C,
    int M, int N)
{
    extern __shared__ float smem[];
    float* Abuf[2] = { smem,          smem + STAGEF };
    float* Bbuf[2] = { smem + ASZ,    smem + STAGEF + ASZ };
    const uint32_t sbase = smem_u32(smem);

    const int tid  = threadIdx.x;
    const int wid  = tid >> 5;
    const int lane = tid & 31;
    const int wm   = wid & 1;
    const int wn   = wid >> 1;
    const int lq   = lane >> 2;
    const int kq   = lane & 3;
    const int m0 = blockIdx.y * BM;
    const int n0 = blockIdx.x * BN;

    const int lrow = tid >> 3;
    const int lcol = (tid & 7) * 4;
    const float* Ag = A + (size_t)(m0 + lrow) * GK + lcol;
    const float* Bg = B + (size_t)(n0 + lrow) * GK + lcol;
    uint32_t sAaddr[2], sBaddr[2];
    #pragma unroll
    for (int s = 0; s < 2; ++s) {
        sAaddr[s] = sbase + (uint32_t)((Abuf[s] - smem) + lrow * SA + lcol) * 4u;
        sBaddr[s] = sbase + (uint32_t)((Bbuf[s] - smem) + lrow * SA + lcol) * 4u;
    }

    float c[4][4][4];
    #pragma unroll
    for (int i = 0; i < 4; ++i)
        #pragma unroll
        for (int j = 0; j < 4; ++j)
            #pragma unroll
            for (int r = 0; r < 4; ++r) c[i][j][r] = 0.f;

    #pragma unroll
    for (int i = 0; i < 4; ++i) {
        const int rs = i * 32;
        cp_async16(sAaddr[0] + (uint32_t)(rs * SA) * 4u, Ag + (size_t)rs * GK);
        cp_async16(sBaddr[0] + (uint32_t)(rs * SA) * 4u, Bg + (size_t)rs * GK);
    }
    CP_ASYNC_COMMIT();

    const int aoff = (wm * 64 + lq) * SA + kq;
    const int boff = (wn * 32 + lq) * SA + kq;

    for (int kt = 0; kt < KTILES; ++kt) {
        const int buf = kt & 1;
        if (kt + 1 < KTILES) {
            const int nb = (kt + 1) & 1;
            const int k0 = (kt + 1) * BK;
            #pragma unroll
            for (int i = 0; i < 4; ++i) {
                const int rs = i * 32;
                cp_async16(sAaddr[nb] + (uint32_t)(rs * SA) * 4u, Ag + (size_t)rs * GK + k0);
                cp_async16(sBaddr[nb] + (uint32_t)(rs * SA) * 4u, Bg + (size_t)rs * GK + k0);
            }
            CP_ASYNC_COMMIT();
            CP_ASYNC_WAIT(1);
        } else {
            CP_ASYNC_WAIT(0);
        }
        __syncthreads();

        const float* As = Abuf[buf];
        const float* Bs = Bbuf[buf];
        #pragma unroll
        for (int ks = 0; ks < 4; ++ks) {
            const int kk = ks * 8;
            uint32_t a[4][4], b[4][2];
            #pragma unroll
            for (int mf = 0; mf < 4; ++mf) {
                const int base = aoff + mf * 16 * SA + kk;
                a[mf][0] = f2tf32(As[base]);
                a[mf][1] = f2tf32(As[base + 8 * SA]);
                a[mf][2] = f2tf32(As[base + 4]);
                a[mf][3] = f2tf32(As[base + 8 * SA + 4]);
            }
            #pragma unroll
            for (int nf = 0; nf < 4; ++nf) {
                const int base = boff + nf * 8 * SA + kk;
                b[nf][0] = f2tf32(Bs[base]);
                b[nf][1] = f2tf32(Bs[base + 4]);
            }
            #pragma unroll
            for (int mf = 0; mf < 4; ++mf)
                #pragma unroll
                for (int nf = 0; nf < 4; ++nf)
                    mma_tf32(c[mf][nf], a[mf][0], a[mf][1], a[mf][2], a[mf][3],
                             b[nf][0], b[nf][1]);
        }
        __syncthreads();
    }

    const int crow = m0 + wm * 64 + lq;
    const int ccol = n0 + wn * 32 + (lane & 3) * 2;
    #pragma unroll
    for (int nf = 0; nf < 4; ++nf) {
        const int col = ccol + nf * 8;
        const float2 bb = *(const float2*)(bias + col);
        #pragma unroll
        for (int mf = 0; mf < 4; ++mf) {
            const int row = crow + mf * 16;
            float2 v0, v1;
            v0.x = c[mf][nf][0] + bb.x; v0.y = c[mf][nf][1] + bb.y;
            v1.x = c[mf][nf][2] + bb.x; v1.y = c[mf][nf][3] + bb.y;
            *(float2*)(C + (size_t)row * N + col)       = v0;
            *(float2*)(C + (size_t)(row + 8) * N + col) = v1;
        }
    }
}

// ===========================================================================
// Tensor-core causal flash attention (tf32 mma.sync).
// Block: one (b, h, 128-q-row tile), 256 threads = 8 warps, 16 q rows/warp.
// KV tiles of 64. SMEM tiles hold tf32-converted data (scale folded into Q).
//   Qs: 128 x 68   Ks: 64 x 68   Vs: 64 x 72   Ps: 128 x 68 (per-warp slabs)
// ===========================================================================
#define AQS 68
#define AVS 72
#define FA_SMEM_FLOATS (128*AQS + 64*AQS + 64*AVS + 128*AQS)
#define FA_SMEM_BYTES  (FA_SMEM_FLOATS*4)   // 105472

__global__ __launch_bounds__(256, 2) void flash_attn_tc(
    const float* __restrict__ qkv, float* __restrict__ out)
{
    extern __shared__ float fsm[];
    float* Qs = fsm;                       // 128 x AQS
    float* Ks = Qs + 128 * AQS;            // 64 x AQS
    float* Vs = Ks + 64 * AQS;             // 64 x AVS
    float* Ps = Vs + 64 * AVS;             // 128 x AQS

    const int tid  = threadIdx.x;
    const int wid  = tid >> 5;
    const int lane = tid & 31;
    const int lq   = lane >> 2;
    const int kq   = lane & 3;
    const int qt   = gridDim.x - 1 - blockIdx.x;   // big blocks first
    const int h    = blockIdx.y;
    const int b    = blockIdx.z;
    const int qbase = qt * 128;
    const int qw    = qbase + wid * 16;            // this warp's first q row

    // ---- stage Q (scaled by 1/8, tf32) ----
    {
        const int r  = tid >> 2;          // 0..63
        const int cg = (tid & 3) * 16;    // 0,16,32,48
        #pragma unroll
        for (int p = 0; p < 2; ++p) {
            const int row = r + p * 64;
            const float* src = qkv + ((size_t)b * SEQ + qbase + row) * C3 + h * HD + cg;
            #pragma unroll
            for (int i = 0; i < 4; ++i) {
                float4 v = __ldg((const float4*)(src + i * 4));
                float* dst = Qs + row * AQS + cg + i * 4;
                dst[0] = f2tf32f(v.x * 0.125f);
                dst[1] = f2tf32f(v.y * 0.125f);
                dst[2] = f2tf32f(v.z * 0.125f);
                dst[3] = f2tf32f(v.w * 0.125f);
            }
        }
    }

    float o[8][4];
    #pragma unroll
    for (int nf = 0; nf < 8; ++nf)
        #pragma unroll
        for (int j = 0; j < 4; ++j) o[nf][j] = 0.f;
    float m0 = -1e30f, m1 = -1e30f, l0 = 0.f, l1 = 0.f;

    const int ntiles = (qt + 1) * 2;
    const int Abase = (wid * 16 + lq) * AQS;       // A-frag row base (Qs / Ps)

    for (int t = 0; t < ntiles; ++t) {
        const int j0 = t * 64;
        __syncthreads();   // protect K/V/P from previous iteration readers
        // ---- stage K, V (tf32) ----
        {
            const int r  = tid >> 2;
            const int cg = (tid & 3) * 16;
            const float* kb = qkv + ((size_t)b * SEQ + j0 + r) * C3 + CH + h * HD + cg;
            const float* vb = kb + CH;
            #pragma unroll
            for (int i = 0; i < 4; ++i) {
                float4 kv4 = __ldg((const float4*)(kb + i * 4));
                float* kd = Ks + r * AQS + cg + i * 4;
                kd[0] = f2tf32f(kv4.x); kd[1] = f2tf32f(kv4.y);
                kd[2] = f2tf32f(kv4.z); kd[3] = f2tf32f(kv4.w);
                float4 vv4 = __ldg((const float4*)(vb + i * 4));
                float* vd = Vs + r * AVS + cg + i * 4;
                vd[0] = f2tf32f(vv4.x); vd[1] = f2tf32f(vv4.y);
                vd[2] = f2tf32f(vv4.z); vd[3] = f2tf32f(vv4.w);
            }
        }
        __syncthreads();

        if (j0 > qw + 15) continue;   // warp fully above diagonal: skip compute

        // ---- S = Q @ K^T ----
        float s[8][4];
        #pragma unroll
        for (int nf = 0; nf < 8; ++nf)
            #pragma unroll
            for (int j = 0; j < 4; ++j) s[nf][j] = 0.f;

        #pragma unroll
        for (int kc = 0; kc < 8; ++kc) {
            const int ab = Abase + kc * 8 + kq;
            const uint32_t a0 = __float_as_uint(Qs[ab]);
            const uint32_t a1 = __float_as_uint(Qs[ab + 8 * AQS]);
            const uint32_t a2 = __float_as_uint(Qs[ab + 4]);
            const uint32_t a3 = __float_as_uint(Qs[ab + 8 * AQS + 4]);
            #pragma unroll
            for (int nf = 0; nf < 8; ++nf) {
                const int bb = (nf * 8 + lq) * AQS + kc * 8 + kq;
                mma_tf32(s[nf], a0, a1, a2, a3,
                         __float_as_uint(Ks[bb]), __float_as_uint(Ks[bb + 4]));
            }
        }

        // ---- causal mask (diagonal-overlap tiles only) ----
        if (j0 + 63 > qw) {
            const int r0 = qw + lq, r1 = r0 + 8;
            #pragma unroll
            for (int nf = 0; nf < 8; ++nf) {
                const int col = j0 + nf * 8 + 2 * kq;
                if (col     > r0) s[nf][0] = -1e30f;
                if (col + 1 > r0) s[nf][1] = -1e30f;
                if (col     > r1) s[nf][2] = -1e30f;
                if (col + 1 > r1) s[nf][3] = -1e30f;
            }
        }

        // ---- online softmax ----
        float tm0 = -1e30f, tm1 = -1e30f;
        #pragma unroll
        for (int nf = 0; nf < 8; ++nf) {
            tm0 = fmaxf(tm0, fmaxf(s[nf][0], s[nf][1]));
            tm1 = fmaxf(tm1, fmaxf(s[nf][2], s[nf][3]));
        }
        tm0 = fmaxf(tm0, __shfl_xor_sync(0xffffffffu, tm0, 1));
        tm0 = fmaxf(tm0, __shfl_xor_sync(0xffffffffu, tm0, 2));
        tm1 = fmaxf(tm1, __shfl_xor_sync(0xffffffffu, tm1, 1));
        tm1 = fmaxf(tm1, __shfl_xor_sync(0xffffffffu, tm1, 2));

        const float nm0 = fmaxf(m0, tm0);
        const float nm1 = fmaxf(m1, tm1);
        const float corr0 = __expf(m0 - nm0);
        const float corr1 = __expf(m1 - nm1);
        m0 = nm0; m1 = nm1;

        float sum0 = 0.f, sum1 = 0.f;
        float* prow0 = Ps + Abase;                 // row wid*16+lq
        float* prow1 = prow0 + 8 * AQS;            // row wid*16+lq+8
        #pragma unroll
        for (int nf = 0; nf < 8; ++nf) {
            const float p0 = __expf(s[nf][0] - nm0);
            const float p1 = __expf(s[nf][1] - nm0);
            const float p2 = __expf(s[nf][2] - nm1);
            const float p3 = __expf(s[nf][3] - nm1);
            sum0 += p0 + p1;
            sum1 += p2 + p3;
            const int cc = nf * 8 + 2 * kq;
            prow0[cc]     = f2tf32f(p0);
            prow0[cc + 1] = f2tf32f(p1);
            prow1[cc]     = f2tf32f(p2);
            prow1[cc + 1] = f2tf32f(p3);
        }
        sum0 += __shfl_xor_sync(0xffffffffu, sum0, 1);
        sum0 += __shfl_xor_sync(0xffffffffu, sum0, 2);
        sum1 += __shfl_xor_sync(0xffffffffu, sum1, 1);
        sum1 += __shfl_xor_sync(0xffffffffu, sum1, 2);
        l0 = l0 * corr0 + sum0;
        l1 = l1 * corr1 + sum1;

        #pragma unroll
        for (int nf = 0; nf < 8; ++nf) {
            o[nf][0] *= corr0; o[nf][1] *= corr0;
            o[nf][2] *= corr1; o[nf][3] *= corr1;
        }

        __syncwarp();   // P slab written by all quad lanes before A-frag reads

        // ---- O += P @ V ----
        #pragma unroll
        for (int kc = 0; kc < 8; ++kc) {
            const int ab = Abase + kc * 8 + kq;
            const uint32_t a0 = __float_as_uint(Ps[ab]);
            const uint32_t a1 = __float_as_uint(Ps[ab + 8 * AQS]);
            const uint32_t a2 = __float_as_uint(Ps[ab + 4]);
            const uint32_t a3 = __float_as_uint(Ps[ab + 8 * AQS + 4]);
            #pragma unroll
            for (int nf = 0; nf < 8; ++nf) {
                const int bb = (kc * 8 + kq) * AVS + nf * 8 + lq;
                mma_tf32(o[nf], a0, a1, a2, a3,
                         __float_as_uint(Vs[bb]), __float_as_uint(Vs[bb + 4 * AVS]));
            }
        }
    }

    // ---- epilogue ----
    const float inv0 = 1.f / l0;
    const float inv1 = 1.f / l1;
    const int row0 = qw + lq;
    float* op0 = out + ((size_t)b * SEQ + row0) * CH + h * HD;
    float* op1 = op0 + (size_t)8 * CH;
    #pragma unroll
    for (int nf = 0; nf < 8; ++nf) {
        const int cc = nf * 8 + 2 * kq;
        float2 v0, v1;
        v0.x = o[nf][0] * inv0; v0.y = o[nf][1] * inv0;
        v1.x = o[nf][2] * inv1; v1.y = o[nf][3] * inv1;
        *(float2*)(op0 + cc) = v0;
        *(float2*)(op1 + cc) = v1;
    }
}

// ---------------------------------------------------------------------------
extern "C" void kernel_launch(void* const* d_in, const int* in_sizes, int n_in,
                              void* d_out, int out_size)
{
    const float* x      = (const float*)d_in[0];  // [B,T,C]
    const float* W_attn = (const float*)d_in[1];  // [3C,C]
    const float* b_attn = (const float*)d_in[2];  // [3C]
    const float* W_proj = (const float*)d_in[3];  // [C,C]
    const float* b_proj = (const float*)d_in[4];  // [C]
    float* out = (float*)d_out;                   // [B,T,C]

    float* qkv; cudaGetSymbolAddress((void**)&qkv, g_qkv);
    float* att; cudaGetSymbolAddress((void**)&att, g_att);

    cudaFuncSetAttribute(gemm_mma_tf32,
                         cudaFuncAttributeMaxDynamicSharedMemorySize, GEMM_SMEM_BYTES);
    cudaFuncSetAttribute(flash_attn_tc,
                         cudaFuncAttributeMaxDynamicSharedMemorySize, FA_SMEM_BYTES);

    const int M = BATCH * SEQ;  // 8192

    // 1) QKV projection: [8192,1024] x [3072,1024]^T -> [8192,3072]
    {
        dim3 grid(C3 / BN, M / BM);
        gemm_mma_tf32<<<grid, 256, GEMM_SMEM_BYTES>>>(x, W_attn, b_attn, qkv, M, C3);
    }
    // 2) causal flash attention (tensor cores) -> g_att [8192,1024]
    {
        dim3 grid(SEQ / 128, NHEAD, BATCH);
        flash_attn_tc<<<grid, 256, FA_SMEM_BYTES>>>(qkv, att);
    }
    // 3) output projection: [8192,1024] x [1024,1024]^T -> [8192,1024]
    {
        dim3 grid(CH / BN, M / BM);
        gemm_mma_tf32<<<grid, 256, GEMM_SMEM_BYTES>>>(att, W_proj, b_proj, out, M, CH);
    }
}

// round 5
// speedup vs baseline: 3.2182x; 1.0387x over previous
#include <cuda_runtime.h>
#include <cstdint>

// Problem constants
#define BATCH 4
#define SEQ   2048
#define CH    1024
#define NHEAD 16
#define HD    64
#define C3    (3*CH)

// Scratch (no cudaMalloc allowed)
__device__ float g_qkv[(size_t)BATCH * SEQ * C3];   // 96 MB
__device__ float g_att[(size_t)BATCH * SEQ * CH];   // 32 MB (written tf32-rounded)
__device__ float g_xs [(size_t)BATCH * SEQ * CH];   // 32 MB  x pre-rounded to tf32
__device__ float g_was[(size_t)C3 * CH];            // 12 MB  W_attn tf32
__device__ float g_wps[(size_t)CH * CH];            //  4 MB  W_proj tf32

// ===========================================================================
// Common helpers
// ===========================================================================
__device__ __forceinline__ uint32_t smem_u32(const void* p) {
    uint32_t a;
    asm("{ .reg .u64 t; cvta.to.shared.u64 t, %1; cvt.u32.u64 %0, t; }" : "=r"(a) : "l"(p));
    return a;
}

__device__ __forceinline__ void cp_async16(uint32_t smem_addr, const void* gptr) {
    asm volatile("cp.async.cg.shared.global [%0], [%1], 16;" :: "r"(smem_addr), "l"(gptr));
}
#define CP_ASYNC_COMMIT() asm volatile("cp.async.commit_group;" ::: "memory")
#define CP_ASYNC_WAIT(n)  asm volatile("cp.async.wait_group %0;" :: "n"(n) : "memory")

__device__ __forceinline__ uint32_t f2tf32(float f) {
    uint32_t r;
    asm("cvt.rna.tf32.f32 %0, %1;" : "=r"(r) : "f"(f));
    return r;
}
__device__ __forceinline__ float f2tf32f(float f) {
    return __uint_as_float(f2tf32(f));
}

__device__ __forceinline__ void mma_tf32(float* c,
    uint32_t a0, uint32_t a1, uint32_t a2, uint32_t a3, uint32_t b0, uint32_t b1)
{
    asm volatile(
        "mma.sync.aligned.m16n8k8.row.col.f32.tf32.tf32.f32 "
        "{%0,%1,%2,%3}, {%4,%5,%6,%7}, {%8,%9}, {%0,%1,%2,%3};"
        : "+f"(c[0]), "+f"(c[1]), "+f"(c[2]), "+f"(c[3])
        : "r"(a0), "r"(a1), "r"(a2), "r"(a3), "r"(b0), "r"(b1));
}

// ===========================================================================
// Elementwise tf32 pre-round: out[i] = tf32(in[i])  (float4 vectorized)
// ===========================================================================
__global__ __launch_bounds__(256) void cvt_tf32_kernel(
    const float4* __restrict__ in, float4* __restrict__ out, int n4)
{
    const int i = blockIdx.x * blockDim.x + threadIdx.x;
    if (i < n4) {
        float4 v = in[i];
        v.x = f2tf32f(v.x); v.y = f2tf32f(v.y);
        v.z = f2tf32f(v.z); v.w = f2tf32f(v.w);
        out[i] = v;
    }
}

// ===========================================================================
// mma.sync tf32 GEMM: C = A @ B^T + bias.  Inputs PRE-ROUNDED to tf32.
// CTA tile 128x128, BK=32, 256 threads (8 warps 2x4), warp tile 64x32.
// cp.async double-buffered; inner loop is pure LDS + HMMA.
// ===========================================================================
#define GK   1024
#define BM   128
#define BN   128
#define BK   32
#define KTILES (GK/BK)
#define SA   36
#define ASZ  (BM*SA)
#define BSZ  (BN*SA)
#define STAGEF (ASZ+BSZ)
#define GEMM_SMEM_BYTES (2*STAGEF*4)

__global__ __launch_bounds__(256, 2) void gemm_mma_tf32(
    const float* __restrict__ A, const float* __restrict__ B,
    const float* __restrict__ bias, float* __restrict__ C,
    int M, int N)
{
    extern __shared__ float smem[];
    float* Abuf[2] = { smem,          smem + STAGEF };
    float* Bbuf[2] = { smem + ASZ,    smem + STAGEF + ASZ };
    const uint32_t sbase = smem_u32(smem);

    const int tid  = threadIdx.x;
    const int wid  = tid >> 5;
    const int lane = tid & 31;
    const int wm   = wid & 1;
    const int wn   = wid >> 1;
    const int lq   = lane >> 2;
    const int kq   = lane & 3;
    const int m0 = blockIdx.y * BM;
    const int n0 = blockIdx.x * BN;

    const int lrow = tid >> 3;
    const int lcol = (tid & 7) * 4;
    const float* Ag = A + (size_t)(m0 + lrow) * GK + lcol;
    const float* Bg = B + (size_t)(n0 + lrow) * GK + lcol;
    uint32_t sAaddr[2], sBaddr[2];
    #pragma unroll
    for (int s = 0; s < 2; ++s) {
        sAaddr[s] = sbase + (uint32_t)((Abuf[s] - smem) + lrow * SA + lcol) * 4u;
        sBaddr[s] = sbase + (uint32_t)((Bbuf[s] - smem) + lrow * SA + lcol) * 4u;
    }

    float c[4][4][4];
    #pragma unroll
    for (int i = 0; i < 4; ++i)
        #pragma unroll
        for (int j = 0; j < 4; ++j)
            #pragma unroll
            for (int r = 0; r < 4; ++r) c[i][j][r] = 0.f;

    #pragma unroll
    for (int i = 0; i < 4; ++i) {
        const int rs = i * 32;
        cp_async16(sAaddr[0] + (uint32_t)(rs * SA) * 4u, Ag + (size_t)rs * GK);
        cp_async16(sBaddr[0] + (uint32_t)(rs * SA) * 4u, Bg + (size_t)rs * GK);
    }
    CP_ASYNC_COMMIT();

    const int aoff = (wm * 64 + lq) * SA + kq;
    const int boff = (wn * 32 + lq) * SA + kq;

    for (int kt = 0; kt < KTILES; ++kt) {
        const int buf = kt & 1;
        if (kt + 1 < KTILES) {
            const int nb = (kt + 1) & 1;
            const int k0 = (kt + 1) * BK;
            #pragma unroll
            for (int i = 0; i < 4; ++i) {
                const int rs = i * 32;
                cp_async16(sAaddr[nb] + (uint32_t)(rs * SA) * 4u, Ag + (size_t)rs * GK + k0);
                cp_async16(sBaddr[nb] + (uint32_t)(rs * SA) * 4u, Bg + (size_t)rs * GK + k0);
            }
            CP_ASYNC_COMMIT();
            CP_ASYNC_WAIT(1);
        } else {
            CP_ASYNC_WAIT(0);
        }
        __syncthreads();

        const uint32_t* As = (const uint32_t*)Abuf[buf];
        const uint32_t* Bs = (const uint32_t*)Bbuf[buf];
        #pragma unroll
        for (int ks = 0; ks < 4; ++ks) {
            const int kk = ks * 8;
            uint32_t a[4][4], b[4][2];
            #pragma unroll
            for (int mf = 0; mf < 4; ++mf) {
                const int base = aoff + mf * 16 * SA + kk;
                a[mf][0] = As[base];
                a[mf][1] = As[base + 8 * SA];
                a[mf][2] = As[base + 4];
                a[mf][3] = As[base + 8 * SA + 4];
            }
            #pragma unroll
            for (int nf = 0; nf < 4; ++nf) {
                const int base = boff + nf * 8 * SA + kk;
                b[nf][0] = Bs[base];
                b[nf][1] = Bs[base + 4];
            }
            #pragma unroll
            for (int mf = 0; mf < 4; ++mf)
                #pragma unroll
                for (int nf = 0; nf < 4; ++nf)
                    mma_tf32(c[mf][nf], a[mf][0], a[mf][1], a[mf][2], a[mf][3],
                             b[nf][0], b[nf][1]);
        }
        __syncthreads();
    }

    const int crow = m0 + wm * 64 + lq;
    const int ccol = n0 + wn * 32 + (lane & 3) * 2;
    #pragma unroll
    for (int nf = 0; nf < 4; ++nf) {
        const int col = ccol + nf * 8;
        const float2 bb = *(const float2*)(bias + col);
        #pragma unroll
        for (int mf = 0; mf < 4; ++mf) {
            const int row = crow + mf * 16;
            float2 v0, v1;
            v0.x = c[mf][nf][0] + bb.x; v0.y = c[mf][nf][1] + bb.y;
            v1.x = c[mf][nf][2] + bb.x; v1.y = c[mf][nf][3] + bb.y;
            *(float2*)(C + (size_t)row * N + col)       = v0;
            *(float2*)(C + (size_t)(row + 8) * N + col) = v1;
        }
    }
}

// ===========================================================================
// Tensor-core causal flash attention (tf32 mma.sync).  Unchanged from R4
// except the epilogue writes tf32-rounded output (feeds proj GEMM directly).
// ===========================================================================
#define AQS 68
#define AVS 72
#define FA_SMEM_FLOATS (128*AQS + 64*AQS + 64*AVS + 128*AQS)
#define FA_SMEM_BYTES  (FA_SMEM_FLOATS*4)   // 105472

__global__ __launch_bounds__(256, 2) void flash_attn_tc(
    const float* __restrict__ qkv, float* __restrict__ out)
{
    extern __shared__ float fsm[];
    float* Qs = fsm;                       // 128 x AQS
    float* Ks = Qs + 128 * AQS;            // 64 x AQS
    float* Vs = Ks + 64 * AQS;             // 64 x AVS
    float* Ps = Vs + 64 * AVS;             // 128 x AQS

    const int tid  = threadIdx.x;
    const int wid  = tid >> 5;
    const int lane = tid & 31;
    const int lq   = lane >> 2;
    const int kq   = lane & 3;
    const int qt   = gridDim.x - 1 - blockIdx.x;   // big blocks first
    const int h    = blockIdx.y;
    const int b    = blockIdx.z;
    const int qbase = qt * 128;
    const int qw    = qbase + wid * 16;

    // ---- stage Q (scaled by 1/8, tf32) ----
    {
        const int r  = tid >> 2;
        const int cg = (tid & 3) * 16;
        #pragma unroll
        for (int p = 0; p < 2; ++p) {
            const int row = r + p * 64;
            const float* src = qkv + ((size_t)b * SEQ + qbase + row) * C3 + h * HD + cg;
            #pragma unroll
            for (int i = 0; i < 4; ++i) {
                float4 v = __ldg((const float4*)(src + i * 4));
                float* dst = Qs + row * AQS + cg + i * 4;
                dst[0] = f2tf32f(v.x * 0.125f);
                dst[1] = f2tf32f(v.y * 0.125f);
                dst[2] = f2tf32f(v.z * 0.125f);
                dst[3] = f2tf32f(v.w * 0.125f);
            }
        }
    }

    float o[8][4];
    #pragma unroll
    for (int nf = 0; nf < 8; ++nf)
        #pragma unroll
        for (int j = 0; j < 4; ++j) o[nf][j] = 0.f;
    float m0 = -1e30f, m1 = -1e30f, l0 = 0.f, l1 = 0.f;

    const int ntiles = (qt + 1) * 2;
    const int Abase = (wid * 16 + lq) * AQS;

    for (int t = 0; t < ntiles; ++t) {
        const int j0 = t * 64;
        __syncthreads();
        // ---- stage K, V (tf32) ----
        {
            const int r  = tid >> 2;
            const int cg = (tid & 3) * 16;
            const float* kb = qkv + ((size_t)b * SEQ + j0 + r) * C3 + CH + h * HD + cg;
            const float* vb = kb + CH;
            #pragma unroll
            for (int i = 0; i < 4; ++i) {
                float4 kv4 = __ldg((const float4*)(kb + i * 4));
                float* kd = Ks + r * AQS + cg + i * 4;
                kd[0] = f2tf32f(kv4.x); kd[1] = f2tf32f(kv4.y);
                kd[2] = f2tf32f(kv4.z); kd[3] = f2tf32f(kv4.w);
                float4 vv4 = __ldg((const float4*)(vb + i * 4));
                float* vd = Vs + r * AVS + cg + i * 4;
                vd[0] = f2tf32f(vv4.x); vd[1] = f2tf32f(vv4.y);
                vd[2] = f2tf32f(vv4.z); vd[3] = f2tf32f(vv4.w);
            }
        }
        __syncthreads();

        if (j0 > qw + 15) continue;

        // ---- S = Q @ K^T ----
        float s[8][4];
        #pragma unroll
        for (int nf = 0; nf < 8; ++nf)
            #pragma unroll
            for (int j = 0; j < 4; ++j) s[nf][j] = 0.f;

        #pragma unroll
        for (int kc = 0; kc < 8; ++kc) {
            const int ab = Abase + kc * 8 + kq;
            const uint32_t a0 = __float_as_uint(Qs[ab]);
            const uint32_t a1 = __float_as_uint(Qs[ab + 8 * AQS]);
            const uint32_t a2 = __float_as_uint(Qs[ab + 4]);
            const uint32_t a3 = __float_as_uint(Qs[ab + 8 * AQS + 4]);
            #pragma unroll
            for (int nf = 0; nf < 8; ++nf) {
                const int bb = (nf * 8 + lq) * AQS + kc * 8 + kq;
                mma_tf32(s[nf], a0, a1, a2, a3,
                         __float_as_uint(Ks[bb]), __float_as_uint(Ks[bb + 4]));
            }
        }

        // ---- causal mask ----
        if (j0 + 63 > qw) {
            const int r0 = qw + lq, r1 = r0 + 8;
            #pragma unroll
            for (int nf = 0; nf < 8; ++nf) {
                const int col = j0 + nf * 8 + 2 * kq;
                if (col     > r0) s[nf][0] = -1e30f;
                if (col + 1 > r0) s[nf][1] = -1e30f;
                if (col     > r1) s[nf][2] = -1e30f;
                if (col + 1 > r1) s[nf][3] = -1e30f;
            }
        }

        // ---- online softmax ----
        float tm0 = -1e30f, tm1 = -1e30f;
        #pragma unroll
        for (int nf = 0; nf < 8; ++nf) {
            tm0 = fmaxf(tm0, fmaxf(s[nf][0], s[nf][1]));
            tm1 = fmaxf(tm1, fmaxf(s[nf][2], s[nf][3]));
        }
        tm0 = fmaxf(tm0, __shfl_xor_sync(0xffffffffu, tm0, 1));
        tm0 = fmaxf(tm0, __shfl_xor_sync(0xffffffffu, tm0, 2));
        tm1 = fmaxf(tm1, __shfl_xor_sync(0xffffffffu, tm1, 1));
        tm1 = fmaxf(tm1, __shfl_xor_sync(0xffffffffu, tm1, 2));

        const float nm0 = fmaxf(m0, tm0);
        const float nm1 = fmaxf(m1, tm1);
        const float corr0 = __expf(m0 - nm0);
        const float corr1 = __expf(m1 - nm1);
        m0 = nm0; m1 = nm1;

        float sum0 = 0.f, sum1 = 0.f;
        float* prow0 = Ps + Abase;
        float* prow1 = prow0 + 8 * AQS;
        #pragma unroll
        for (int nf = 0; nf < 8; ++nf) {
            const float p0 = __expf(s[nf][0] - nm0);
            const float p1 = __expf(s[nf][1] - nm0);
            const float p2 = __expf(s[nf][2] - nm1);
            const float p3 = __expf(s[nf][3] - nm1);
            sum0 += p0 + p1;
            sum1 += p2 + p3;
            const int cc = nf * 8 + 2 * kq;
            prow0[cc]     = f2tf32f(p0);
            prow0[cc + 1] = f2tf32f(p1);
            prow1[cc]     = f2tf32f(p2);
            prow1[cc + 1] = f2tf32f(p3);
        }
        sum0 += __shfl_xor_sync(0xffffffffu, sum0, 1);
        sum0 += __shfl_xor_sync(0xffffffffu, sum0, 2);
        sum1 += __shfl_xor_sync(0xffffffffu, sum1, 1);
        sum1 += __shfl_xor_sync(0xffffffffu, sum1, 2);
        l0 = l0 * corr0 + sum0;
        l1 = l1 * corr1 + sum1;

        #pragma unroll
        for (int nf = 0; nf < 8; ++nf) {
            o[nf][0] *= corr0; o[nf][1] *= corr0;
            o[nf][2] *= corr1; o[nf][3] *= corr1;
        }

        __syncwarp();

        // ---- O += P @ V ----
        #pragma unroll
        for (int kc = 0; kc < 8; ++kc) {
            const int ab = Abase + kc * 8 + kq;
            const uint32_t a0 = __float_as_uint(Ps[ab]);
            const uint32_t a1 = __float_as_uint(Ps[ab + 8 * AQS]);
            const uint32_t a2 = __float_as_uint(Ps[ab + 4]);
            const uint32_t a3 = __float_as_uint(Ps[ab + 8 * AQS + 4]);
            #pragma unroll
            for (int nf = 0; nf < 8; ++nf) {
                const int bb = (kc * 8 + kq) * AVS + nf * 8 + lq;
                mma_tf32(o[nf], a0, a1, a2, a3,
                         __float_as_uint(Vs[bb]), __float_as_uint(Vs[bb + 4 * AVS]));
            }
        }
    }

    // ---- epilogue (tf32-rounded output: proj GEMM consumes it cvt-free) ----
    const float inv0 = 1.f / l0;
    const float inv1 = 1.f / l1;
    const int row0 = qw + lq;
    float* op0 = out + ((size_t)b * SEQ + row0) * CH + h * HD;
    float* op1 = op0 + (size_t)8 * CH;
    #pragma unroll
    for (int nf = 0; nf < 8; ++nf) {
        const int cc = nf * 8 + 2 * kq;
        float2 v0, v1;
        v0.x = f2tf32f(o[nf][0] * inv0); v0.y = f2tf32f(o[nf][1] * inv0);
        v1.x = f2tf32f(o[nf][2] * inv1); v1.y = f2tf32f(o[nf][3] * inv1);
        *(float2*)(op0 + cc) = v0;
        *(float2*)(op1 + cc) = v1;
    }
}

// ---------------------------------------------------------------------------
extern "C" void kernel_launch(void* const* d_in, const int* in_sizes, int n_in,
                              void* d_out, int out_size)
{
    const float* x      = (const float*)d_in[0];
    const float* W_attn = (const float*)d_in[1];
    const float* b_attn = (const float*)d_in[2];
    const float* W_proj = (const float*)d_in[3];
    const float* b_proj = (const float*)d_in[4];
    float* out = (float*)d_out;

    float* qkv; cudaGetSymbolAddress((void**)&qkv, g_qkv);
    float* att; cudaGetSymbolAddress((void**)&att, g_att);
    float* xs;  cudaGetSymbolAddress((void**)&xs,  g_xs);
    float* was; cudaGetSymbolAddress((void**)&was, g_was);
    float* wps; cudaGetSymbolAddress((void**)&wps, g_wps);

    cudaFuncSetAttribute(gemm_mma_tf32,
                         cudaFuncAttributeMaxDynamicSharedMemorySize, GEMM_SMEM_BYTES);
    cudaFuncSetAttribute(flash_attn_tc,
                         cudaFuncAttributeMaxDynamicSharedMemorySize, FA_SMEM_BYTES);

    const int M = BATCH * SEQ;  // 8192

    // 0) pre-round GEMM operands to tf32
    {
        const int nx = M * CH / 4, na = C3 * CH / 4, np = CH * CH / 4;
        cvt_tf32_kernel<<<(nx + 255) / 256, 256>>>((const float4*)x,      (float4*)xs,  nx);
        cvt_tf32_kernel<<<(na + 255) / 256, 256>>>((const float4*)W_attn, (float4*)was, na);
        cvt_tf32_kernel<<<(np + 255) / 256, 256>>>((const float4*)W_proj, (float4*)wps, np);
    }
    // 1) QKV projection
    {
        dim3 grid(C3 / BN, M / BM);
        gemm_mma_tf32<<<grid, 256, GEMM_SMEM_BYTES>>>(xs, was, b_attn, qkv, M, C3);
    }
    // 2) causal flash attention (tensor cores)
    {
        dim3 grid(SEQ / 128, NHEAD, BATCH);
        flash_attn_tc<<<grid, 256, FA_SMEM_BYTES>>>(qkv, att);
    }
    // 3) output projection
    {
        dim3 grid(CH / BN, M / BM);
        gemm_mma_tf32<<<grid, 256, GEMM_SMEM_BYTES>>>(att, wps, b_proj, out, M, CH);
    }
}

// round 6
// speedup vs baseline: 3.5773x; 1.1116x over previous
#include <cuda_runtime.h>
#include <cstdint>

// Problem constants
#define BATCH 4
#define SEQ   2048
#define CH    1024
#define NHEAD 16
#define HD    64
#define C3    (3*CH)

// Scratch (no cudaMalloc allowed)
__device__ float g_qkv[(size_t)BATCH * SEQ * C3];   // 96 MB
__device__ float g_att[(size_t)BATCH * SEQ * CH];   // 32 MB (tf32-rounded)
__device__ float g_xs [(size_t)BATCH * SEQ * CH];   // 32 MB  x tf32
__device__ float g_was[(size_t)C3 * CH];            // 12 MB  W_attn tf32
__device__ float g_wps[(size_t)CH * CH];            //  4 MB  W_proj tf32

// ===========================================================================
// Common helpers
// ===========================================================================
__device__ __forceinline__ uint32_t smem_u32(const void* p) {
    uint32_t a;
    asm("{ .reg .u64 t; cvta.to.shared.u64 t, %1; cvt.u32.u64 %0, t; }" : "=r"(a) : "l"(p));
    return a;
}

__device__ __forceinline__ void cp_async16(uint32_t smem_addr, const void* gptr) {
    asm volatile("cp.async.cg.shared.global [%0], [%1], 16;" :: "r"(smem_addr), "l"(gptr));
}
#define CP_ASYNC_COMMIT() asm volatile("cp.async.commit_group;" ::: "memory")
#define CP_ASYNC_WAIT(n)  asm volatile("cp.async.wait_group %0;" :: "n"(n) : "memory")

__device__ __forceinline__ uint32_t f2tf32(float f) {
    uint32_t r;
    asm("cvt.rna.tf32.f32 %0, %1;" : "=r"(r) : "f"(f));
    return r;
}
__device__ __forceinline__ float f2tf32f(float f) {
    return __uint_as_float(f2tf32(f));
}

__device__ __forceinline__ void mma_tf32(float* c,
    uint32_t a0, uint32_t a1, uint32_t a2, uint32_t a3, uint32_t b0, uint32_t b1)
{
    asm volatile(
        "mma.sync.aligned.m16n8k8.row.col.f32.tf32.tf32.f32 "
        "{%0,%1,%2,%3}, {%4,%5,%6,%7}, {%8,%9}, {%0,%1,%2,%3};"
        : "+f"(c[0]), "+f"(c[1]), "+f"(c[2]), "+f"(c[3])
        : "r"(a0), "r"(a1), "r"(a2), "r"(a3), "r"(b0), "r"(b1));
}

// ldmatrix x4 (b16 tiles; for tf32 data each 8x8xb16 tile == 8x4xtf32 tile,
// lane l -> row l/4, tf32-col l%4 — exactly the m16n8k8 tf32 fragment layout)
__device__ __forceinline__ void ldsm4(uint32_t* r, uint32_t addr) {
    asm volatile("ldmatrix.sync.aligned.m8n8.x4.shared.b16 {%0,%1,%2,%3}, [%4];"
        : "=r"(r[0]), "=r"(r[1]), "=r"(r[2]), "=r"(r[3]) : "r"(addr));
}

// ===========================================================================
// Elementwise tf32 pre-round
// ===========================================================================
__global__ __launch_bounds__(256) void cvt_tf32_kernel(
    const float4* __restrict__ in, float4* __restrict__ out, int n4)
{
    const int i = blockIdx.x * blockDim.x + threadIdx.x;
    if (i < n4) {
        float4 v = in[i];
        v.x = f2tf32f(v.x); v.y = f2tf32f(v.y);
        v.z = f2tf32f(v.z); v.w = f2tf32f(v.w);
        out[i] = v;
    }
}

// ===========================================================================
// mma.sync tf32 GEMM: C = A @ B^T + bias.  Inputs PRE-ROUNDED to tf32.
// CTA 128x128, BK=32, 128 threads = 4 warps, warp tile 64x64 (2x2).
// 3-stage cp.async ring; fragments via ldmatrix.x4.
// ===========================================================================
#define GK   1024
#define BM   128
#define BN   128
#define BK   32
#define KTILES (GK/BK)
#define SA   36
#define ASTG (BM*SA)               // floats per A stage
#define STGF (2*ASTG)              // A+B per stage
#define NSTAGE 3
#define GEMM_SMEM_BYTES (NSTAGE*STGF*4)   // 110592

__global__ __launch_bounds__(128, 2) void gemm_mma_tf32(
    const float* __restrict__ A, const float* __restrict__ B,
    const float* __restrict__ bias, float* __restrict__ C,
    int M, int N)
{
    extern __shared__ float smem[];
    const uint32_t sbase = smem_u32(smem);

    const int tid  = threadIdx.x;
    const int wid  = tid >> 5;
    const int lane = tid & 31;
    const int wm   = wid & 1;        // 64-row slab
    const int wn   = wid >> 1;       // 64-col slab
    const int lq   = lane >> 2;
    const int kq   = lane & 3;
    const int m0 = blockIdx.y * BM;
    const int n0 = blockIdx.x * BN;

    // ---- cp.async loader mapping: chunk = tid + i*128; row = chunk>>3, c = chunk&7
    const int lrow = tid >> 3;           // 0..15 (+16 per i)
    const int lc   = (tid & 7) * 4;      // float col
    const float* Ag = A + (size_t)(m0 + lrow) * GK + lc;
    const float* Bg = B + (size_t)(n0 + lrow) * GK + lc;
    const uint32_t sArow = (uint32_t)(lrow * SA + lc) * 4u;   // byte offset within stage A
    const uint32_t sBrow = (uint32_t)(ASTG + lrow * SA + lc) * 4u;

    // ---- ldmatrix per-lane base offsets (bytes) ----
    // A x4 tiles (per mf): t0 rows0-7/k0-3, t1 rows8-15/k0-3, t2 rows0-7/k4-7, t3 rows8-15/k4-7
    const int arow = wm * 64 + (lane & 7) + ((lane & 8) ? 8 : 0);
    const int acol = (lane & 16) ? 4 : 0;
    const uint32_t aoff = (uint32_t)(arow * SA + acol) * 4u;
    // B x4 tiles (per jp = nf pair): t0 n0-7/k0-3, t1 n0-7/k4-7, t2 n8-15/k0-3, t3 n8-15/k4-7
    const int brow = wn * 64 + (lane & 7) + ((lane & 16) ? 8 : 0);
    const int bcol = (lane & 8) ? 4 : 0;
    const uint32_t boff = (uint32_t)(ASTG + brow * SA + bcol) * 4u;

    float c[4][8][4];
    #pragma unroll
    for (int i = 0; i < 4; ++i)
        #pragma unroll
        for (int j = 0; j < 8; ++j)
            #pragma unroll
            for (int r = 0; r < 4; ++r) c[i][j][r] = 0.f;

    // ---- prologue: issue stages 0..2 ----
    #pragma unroll
    for (int s = 0; s < NSTAGE; ++s) {
        const uint32_t sb = sbase + (uint32_t)(s * STGF) * 4u;
        const int k0 = s * BK;
        #pragma unroll
        for (int i = 0; i < 8; ++i) {
            const uint32_t ro = (uint32_t)(i * 16 * SA) * 4u;
            cp_async16(sb + sArow + ro, Ag + (size_t)(i * 16) * GK + k0);
            cp_async16(sb + sBrow + ro, Bg + (size_t)(i * 16) * GK + k0);
        }
        CP_ASYNC_COMMIT();
    }

    for (int kt = 0; kt < KTILES; ++kt) {
        CP_ASYNC_WAIT(2);
        __syncthreads();

        const int st = kt % NSTAGE;
        const uint32_t Ab = sbase + (uint32_t)(st * STGF) * 4u + aoff;
        const uint32_t Bb = sbase + (uint32_t)(st * STGF) * 4u + boff;

        #pragma unroll
        for (int ks = 0; ks < 4; ++ks) {
            const uint32_t kkb = (uint32_t)(ks * 8) * 4u;
            uint32_t a[4][4], b[4][4];
            #pragma unroll
            for (int mf = 0; mf < 4; ++mf)
                ldsm4(a[mf], Ab + (uint32_t)(mf * 16 * SA) * 4u + kkb);
            #pragma unroll
            for (int jp = 0; jp < 4; ++jp)
                ldsm4(b[jp], Bb + (uint32_t)(jp * 16 * SA) * 4u + kkb);
            #pragma unroll
            for (int mf = 0; mf < 4; ++mf)
                #pragma unroll
                for (int jp = 0; jp < 4; ++jp) {
                    mma_tf32(c[mf][2*jp],   a[mf][0], a[mf][1], a[mf][2], a[mf][3],
                             b[jp][0], b[jp][1]);
                    mma_tf32(c[mf][2*jp+1], a[mf][0], a[mf][1], a[mf][2], a[mf][3],
                             b[jp][2], b[jp][3]);
                }
        }
        __syncthreads();

        // refill the stage just consumed with tile kt+3
        if (kt + NSTAGE < KTILES) {
            const uint32_t sb = sbase + (uint32_t)(st * STGF) * 4u;
            const int k0 = (kt + NSTAGE) * BK;
            #pragma unroll
            for (int i = 0; i < 8; ++i) {
                const uint32_t ro = (uint32_t)(i * 16 * SA) * 4u;
                cp_async16(sb + sArow + ro, Ag + (size_t)(i * 16) * GK + k0);
                cp_async16(sb + sBrow + ro, Bg + (size_t)(i * 16) * GK + k0);
            }
        }
        CP_ASYNC_COMMIT();   // uniform group count (possibly empty)
    }

    // ---- epilogue ----
    const int crow = m0 + wm * 64 + lq;
    const int ccol = n0 + wn * 64 + 2 * kq;
    #pragma unroll
    for (int nf = 0; nf < 8; ++nf) {
        const int col = ccol + nf * 8;
        const float2 bb = *(const float2*)(bias + col);
        #pragma unroll
        for (int mf = 0; mf < 4; ++mf) {
            const int row = crow + mf * 16;
            float2 v0, v1;
            v0.x = c[mf][nf][0] + bb.x; v0.y = c[mf][nf][1] + bb.y;
            v1.x = c[mf][nf][2] + bb.x; v1.y = c[mf][nf][3] + bb.y;
            *(float2*)(C + (size_t)row * N + col)       = v0;
            *(float2*)(C + (size_t)(row + 8) * N + col) = v1;
        }
    }
}

// ===========================================================================
// Tensor-core causal flash attention (tf32 mma.sync) — unchanged from R5.
// ===========================================================================
#define AQS 68
#define AVS 72
#define FA_SMEM_FLOATS (128*AQS + 64*AQS + 64*AVS + 128*AQS)
#define FA_SMEM_BYTES  (FA_SMEM_FLOATS*4)   // 105472

__global__ __launch_bounds__(256, 2) void flash_attn_tc(
    const float* __restrict__ qkv, float* __restrict__ out)
{
    extern __shared__ float fsm[];
    float* Qs = fsm;
    float* Ks = Qs + 128 * AQS;
    float* Vs = Ks + 64 * AQS;
    float* Ps = Vs + 64 * AVS;

    const int tid  = threadIdx.x;
    const int wid  = tid >> 5;
    const int lane = tid & 31;
    const int lq   = lane >> 2;
    const int kq   = lane & 3;
    const int qt   = gridDim.x - 1 - blockIdx.x;
    const int h    = blockIdx.y;
    const int b    = blockIdx.z;
    const int qbase = qt * 128;
    const int qw    = qbase + wid * 16;

    {
        const int r  = tid >> 2;
        const int cg = (tid & 3) * 16;
        #pragma unroll
        for (int p = 0; p < 2; ++p) {
            const int row = r + p * 64;
            const float* src = qkv + ((size_t)b * SEQ + qbase + row) * C3 + h * HD + cg;
            #pragma unroll
            for (int i = 0; i < 4; ++i) {
                float4 v = __ldg((const float4*)(src + i * 4));
                float* dst = Qs + row * AQS + cg + i * 4;
                dst[0] = f2tf32f(v.x * 0.125f);
                dst[1] = f2tf32f(v.y * 0.125f);
                dst[2] = f2tf32f(v.z * 0.125f);
                dst[3] = f2tf32f(v.w * 0.125f);
            }
        }
    }

    float o[8][4];
    #pragma unroll
    for (int nf = 0; nf < 8; ++nf)
        #pragma unroll
        for (int j = 0; j < 4; ++j) o[nf][j] = 0.f;
    float m0 = -1e30f, m1 = -1e30f, l0 = 0.f, l1 = 0.f;

    const int ntiles = (qt + 1) * 2;
    const int Abase = (wid * 16 + lq) * AQS;

    for (int t = 0; t < ntiles; ++t) {
        const int j0 = t * 64;
        __syncthreads();
        {
            const int r  = tid >> 2;
            const int cg = (tid & 3) * 16;
            const float* kb = qkv + ((size_t)b * SEQ + j0 + r) * C3 + CH + h * HD + cg;
            const float* vb = kb + CH;
            #pragma unroll
            for (int i = 0; i < 4; ++i) {
                float4 kv4 = __ldg((const float4*)(kb + i * 4));
                float* kd = Ks + r * AQS + cg + i * 4;
                kd[0] = f2tf32f(kv4.x); kd[1] = f2tf32f(kv4.y);
                kd[2] = f2tf32f(kv4.z); kd[3] = f2tf32f(kv4.w);
                float4 vv4 = __ldg((const float4*)(vb + i * 4));
                float* vd = Vs + r * AVS + cg + i * 4;
                vd[0] = f2tf32f(vv4.x); vd[1] = f2tf32f(vv4.y);
                vd[2] = f2tf32f(vv4.z); vd[3] = f2tf32f(vv4.w);
            }
        }
        __syncthreads();

        if (j0 > qw + 15) continue;

        float s[8][4];
        #pragma unroll
        for (int nf = 0; nf < 8; ++nf)
            #pragma unroll
            for (int j = 0; j < 4; ++j) s[nf][j] = 0.f;

        #pragma unroll
        for (int kc = 0; kc < 8; ++kc) {
            const int ab = Abase + kc * 8 + kq;
            const uint32_t a0 = __float_as_uint(Qs[ab]);
            const uint32_t a1 = __float_as_uint(Qs[ab + 8 * AQS]);
            const uint32_t a2 = __float_as_uint(Qs[ab + 4]);
            const uint32_t a3 = __float_as_uint(Qs[ab + 8 * AQS + 4]);
            #pragma unroll
            for (int nf = 0; nf < 8; ++nf) {
                const int bb = (nf * 8 + lq) * AQS + kc * 8 + kq;
                mma_tf32(s[nf], a0, a1, a2, a3,
                         __float_as_uint(Ks[bb]), __float_as_uint(Ks[bb + 4]));
            }
        }

        if (j0 + 63 > qw) {
            const int r0 = qw + lq, r1 = r0 + 8;
            #pragma unroll
            for (int nf = 0; nf < 8; ++nf) {
                const int col = j0 + nf * 8 + 2 * kq;
                if (col     > r0) s[nf][0] = -1e30f;
                if (col + 1 > r0) s[nf][1] = -1e30f;
                if (col     > r1) s[nf][2] = -1e30f;
                if (col + 1 > r1) s[nf][3] = -1e30f;
            }
        }

        float tm0 = -1e30f, tm1 = -1e30f;
        #pragma unroll
        for (int nf = 0; nf < 8; ++nf) {
            tm0 = fmaxf(tm0, fmaxf(s[nf][0], s[nf][1]));
            tm1 = fmaxf(tm1, fmaxf(s[nf][2], s[nf][3]));
        }
        tm0 = fmaxf(tm0, __shfl_xor_sync(0xffffffffu, tm0, 1));
        tm0 = fmaxf(tm0, __shfl_xor_sync(0xffffffffu, tm0, 2));
        tm1 = fmaxf(tm1, __shfl_xor_sync(0xffffffffu, tm1, 1));
        tm1 = fmaxf(tm1, __shfl_xor_sync(0xffffffffu, tm1, 2));

        const float nm0 = fmaxf(m0, tm0);
        const float nm1 = fmaxf(m1, tm1);
        const float corr0 = __expf(m0 - nm0);
        const float corr1 = __expf(m1 - nm1);
        m0 = nm0; m1 = nm1;

        float sum0 = 0.f, sum1 = 0.f;
        float* prow0 = Ps + Abase;
        float* prow1 = prow0 + 8 * AQS;
        #pragma unroll
        for (int nf = 0; nf < 8; ++nf) {
            const float p0 = __expf(s[nf][0] - nm0);
            const float p1 = __expf(s[nf][1] - nm0);
            const float p2 = __expf(s[nf][2] - nm1);
            const float p3 = __expf(s[nf][3] - nm1);
            sum0 += p0 + p1;
            sum1 += p2 + p3;
            const int cc = nf * 8 + 2 * kq;
            prow0[cc]     = f2tf32f(p0);
            prow0[cc + 1] = f2tf32f(p1);
            prow1[cc]     = f2tf32f(p2);
            prow1[cc + 1] = f2tf32f(p3);
        }
        sum0 += __shfl_xor_sync(0xffffffffu, sum0, 1);
        sum0 += __shfl_xor_sync(0xffffffffu, sum0, 2);
        sum1 += __shfl_xor_sync(0xffffffffu, sum1, 1);
        sum1 += __shfl_xor_sync(0xffffffffu, sum1, 2);
        l0 = l0 * corr0 + sum0;
        l1 = l1 * corr1 + sum1;

        #pragma unroll
        for (int nf = 0; nf < 8; ++nf) {
            o[nf][0] *= corr0; o[nf][1] *= corr0;
            o[nf][2] *= corr1; o[nf][3] *= corr1;
        }

        __syncwarp();

        #pragma unroll
        for (int kc = 0; kc < 8; ++kc) {
            const int ab = Abase + kc * 8 + kq;
            const uint32_t a0 = __float_as_uint(Ps[ab]);
            const uint32_t a1 = __float_as_uint(Ps[ab + 8 * AQS]);
            const uint32_t a2 = __float_as_uint(Ps[ab + 4]);
            const uint32_t a3 = __float_as_uint(Ps[ab + 8 * AQS + 4]);
            #pragma unroll
            for (int nf = 0; nf < 8; ++nf) {
                const int bb = (kc * 8 + kq) * AVS + nf * 8 + lq;
                mma_tf32(o[nf], a0, a1, a2, a3,
                         __float_as_uint(Vs[bb]), __float_as_uint(Vs[bb + 4 * AVS]));
            }
        }
    }

    const float inv0 = 1.f / l0;
    const float inv1 = 1.f / l1;
    const int row0 = qw + lq;
    float* op0 = out + ((size_t)b * SEQ + row0) * CH + h * HD;
    float* op1 = op0 + (size_t)8 * CH;
    #pragma unroll
    for (int nf = 0; nf < 8; ++nf) {
        const int cc = nf * 8 + 2 * kq;
        float2 v0, v1;
        v0.x = f2tf32f(o[nf][0] * inv0); v0.y = f2tf32f(o[nf][1] * inv0);
        v1.x = f2tf32f(o[nf][2] * inv1); v1.y = f2tf32f(o[nf][3] * inv1);
        *(float2*)(op0 + cc) = v0;
        *(float2*)(op1 + cc) = v1;
    }
}

// ---------------------------------------------------------------------------
extern "C" void kernel_launch(void* const* d_in, const int* in_sizes, int n_in,
                              void* d_out, int out_size)
{
    const float* x      = (const float*)d_in[0];
    const float* W_attn = (const float*)d_in[1];
    const float* b_attn = (const float*)d_in[2];
    const float* W_proj = (const float*)d_in[3];
    const float* b_proj = (const float*)d_in[4];
    float* out = (float*)d_out;

    float* qkv; cudaGetSymbolAddress((void**)&qkv, g_qkv);
    float* att; cudaGetSymbolAddress((void**)&att, g_att);
    float* xs;  cudaGetSymbolAddress((void**)&xs,  g_xs);
    float* was; cudaGetSymbolAddress((void**)&was, g_was);
    float* wps; cudaGetSymbolAddress((void**)&wps, g_wps);

    cudaFuncSetAttribute(gemm_mma_tf32,
                         cudaFuncAttributeMaxDynamicSharedMemorySize, GEMM_SMEM_BYTES);
    cudaFuncSetAttribute(flash_attn_tc,
                         cudaFuncAttributeMaxDynamicSharedMemorySize, FA_SMEM_BYTES);

    const int M = BATCH * SEQ;  // 8192

    // 0) pre-round GEMM operands to tf32
    {
        const int nx = M * CH / 4, na = C3 * CH / 4, np = CH * CH / 4;
        cvt_tf32_kernel<<<(nx + 255) / 256, 256>>>((const float4*)x,      (float4*)xs,  nx);
        cvt_tf32_kernel<<<(na + 255) / 256, 256>>>((const float4*)W_attn, (float4*)was, na);
        cvt_tf32_kernel<<<(np + 255) / 256, 256>>>((const float4*)W_proj, (float4*)wps, np);
    }
    // 1) QKV projection
    {
        dim3 grid(C3 / BN, M / BM);
        gemm_mma_tf32<<<grid, 128, GEMM_SMEM_BYTES>>>(xs, was, b_attn, qkv, M, C3);
    }
    // 2) causal flash attention
    {
        dim3 grid(SEQ / 128, NHEAD, BATCH);
        flash_attn_tc<<<grid, 256, FA_SMEM_BYTES>>>(qkv, att);
    }
    // 3) output projection
    {
        dim3 grid(CH / BN, M / BM);
        gemm_mma_tf32<<<grid, 128, GEMM_SMEM_BYTES>>>(att, wps, b_proj, out, M, CH);
    }
}

// round 7
// speedup vs baseline: 4.0108x; 1.1212x over previous
#include <cuda_runtime.h>
#include <cstdint>

// Problem constants
#define BATCH 4
#define SEQ   2048
#define CH    1024
#define NHEAD 16
#define HD    64
#define C3    (3*CH)

// Scratch (no cudaMalloc allowed)
__device__ float g_qkv[(size_t)BATCH * SEQ * C3];   // 96 MB (tf32-rounded by GEMM)
__device__ float g_att[(size_t)BATCH * SEQ * CH];   // 32 MB (tf32-rounded)
__device__ float g_xs [(size_t)BATCH * SEQ * CH];   // 32 MB  x tf32
__device__ float g_was[(size_t)C3 * CH];            // 12 MB  W_attn tf32
__device__ float g_wps[(size_t)CH * CH];            //  4 MB  W_proj tf32

// ===========================================================================
// Common helpers
// ===========================================================================
__device__ __forceinline__ uint32_t smem_u32(const void* p) {
    uint32_t a;
    asm("{ .reg .u64 t; cvta.to.shared.u64 t, %1; cvt.u32.u64 %0, t; }" : "=r"(a) : "l"(p));
    return a;
}

__device__ __forceinline__ void cp_async16(uint32_t smem_addr, const void* gptr) {
    asm volatile("cp.async.cg.shared.global [%0], [%1], 16;" :: "r"(smem_addr), "l"(gptr));
}
#define CP_ASYNC_COMMIT() asm volatile("cp.async.commit_group;" ::: "memory")
#define CP_ASYNC_WAIT(n)  asm volatile("cp.async.wait_group %0;" :: "n"(n) : "memory")

__device__ __forceinline__ uint32_t f2tf32(float f) {
    uint32_t r;
    asm("cvt.rna.tf32.f32 %0, %1;" : "=r"(r) : "f"(f));
    return r;
}
__device__ __forceinline__ float f2tf32f(float f) {
    return __uint_as_float(f2tf32(f));
}

__device__ __forceinline__ void mma_tf32(float* c,
    uint32_t a0, uint32_t a1, uint32_t a2, uint32_t a3, uint32_t b0, uint32_t b1)
{
    asm volatile(
        "mma.sync.aligned.m16n8k8.row.col.f32.tf32.tf32.f32 "
        "{%0,%1,%2,%3}, {%4,%5,%6,%7}, {%8,%9}, {%0,%1,%2,%3};"
        : "+f"(c[0]), "+f"(c[1]), "+f"(c[2]), "+f"(c[3])
        : "r"(a0), "r"(a1), "r"(a2), "r"(a3), "r"(b0), "r"(b1));
}

// ldmatrix x4 (b16 tiles; tf32 data: each 8x8xb16 tile == 8x4xtf32 tile,
// lane l -> (row l/4, tf32-col l%4) — the m16n8k8 tf32 fragment layout)
__device__ __forceinline__ void ldsm4(uint32_t* r, uint32_t addr) {
    asm volatile("ldmatrix.sync.aligned.m8n8.x4.shared.b16 {%0,%1,%2,%3}, [%4];"
        : "=r"(r[0]), "=r"(r[1]), "=r"(r[2]), "=r"(r[3]) : "r"(addr));
}

// ===========================================================================
// Elementwise tf32 pre-round
// ===========================================================================
__global__ __launch_bounds__(256) void cvt_tf32_kernel(
    const float4* __restrict__ in, float4* __restrict__ out, int n4)
{
    const int i = blockIdx.x * blockDim.x + threadIdx.x;
    if (i < n4) {
        float4 v = in[i];
        v.x = f2tf32f(v.x); v.y = f2tf32f(v.y);
        v.z = f2tf32f(v.z); v.w = f2tf32f(v.w);
        out[i] = v;
    }
}

// ===========================================================================
// mma.sync tf32 GEMM (R6 structure + round_out flag on the epilogue)
// ===========================================================================
#define GK   1024
#define BM   128
#define BN   128
#define BK   32
#define KTILES (GK/BK)
#define SA   36
#define ASTG (BM*SA)
#define STGF (2*ASTG)
#define NSTAGE 3
#define GEMM_SMEM_BYTES (NSTAGE*STGF*4)

__global__ __launch_bounds__(128, 2) void gemm_mma_tf32(
    const float* __restrict__ A, const float* __restrict__ B,
    const float* __restrict__ bias, float* __restrict__ C,
    int M, int N, int round_out)
{
    extern __shared__ float smem[];
    const uint32_t sbase = smem_u32(smem);

    const int tid  = threadIdx.x;
    const int wid  = tid >> 5;
    const int lane = tid & 31;
    const int wm   = wid & 1;
    const int wn   = wid >> 1;
    const int lq   = lane >> 2;
    const int kq   = lane & 3;
    const int m0 = blockIdx.y * BM;
    const int n0 = blockIdx.x * BN;

    const int lrow = tid >> 3;
    const int lc   = (tid & 7) * 4;
    const float* Ag = A + (size_t)(m0 + lrow) * GK + lc;
    const float* Bg = B + (size_t)(n0 + lrow) * GK + lc;
    const uint32_t sArow = (uint32_t)(lrow * SA + lc) * 4u;
    const uint32_t sBrow = (uint32_t)(ASTG + lrow * SA + lc) * 4u;

    const int arow = wm * 64 + (lane & 7) + ((lane & 8) ? 8 : 0);
    const int acol = (lane & 16) ? 4 : 0;
    const uint32_t aoff = (uint32_t)(arow * SA + acol) * 4u;
    const int brow = wn * 64 + (lane & 7) + ((lane & 16) ? 8 : 0);
    const int bcol = (lane & 8) ? 4 : 0;
    const uint32_t boff = (uint32_t)(ASTG + brow * SA + bcol) * 4u;

    float c[4][8][4];
    #pragma unroll
    for (int i = 0; i < 4; ++i)
        #pragma unroll
        for (int j = 0; j < 8; ++j)
            #pragma unroll
            for (int r = 0; r < 4; ++r) c[i][j][r] = 0.f;

    #pragma unroll
    for (int s = 0; s < NSTAGE; ++s) {
        const uint32_t sb = sbase + (uint32_t)(s * STGF) * 4u;
        const int k0 = s * BK;
        #pragma unroll
        for (int i = 0; i < 8; ++i) {
            const uint32_t ro = (uint32_t)(i * 16 * SA) * 4u;
            cp_async16(sb + sArow + ro, Ag + (size_t)(i * 16) * GK + k0);
            cp_async16(sb + sBrow + ro, Bg + (size_t)(i * 16) * GK + k0);
        }
        CP_ASYNC_COMMIT();
    }

    for (int kt = 0; kt < KTILES; ++kt) {
        CP_ASYNC_WAIT(2);
        __syncthreads();

        const int st = kt % NSTAGE;
        const uint32_t Ab = sbase + (uint32_t)(st * STGF) * 4u + aoff;
        const uint32_t Bb = sbase + (uint32_t)(st * STGF) * 4u + boff;

        #pragma unroll
        for (int ks = 0; ks < 4; ++ks) {
            const uint32_t kkb = (uint32_t)(ks * 8) * 4u;
            uint32_t a[4][4], b[4][4];
            #pragma unroll
            for (int mf = 0; mf < 4; ++mf)
                ldsm4(a[mf], Ab + (uint32_t)(mf * 16 * SA) * 4u + kkb);
            #pragma unroll
            for (int jp = 0; jp < 4; ++jp)
                ldsm4(b[jp], Bb + (uint32_t)(jp * 16 * SA) * 4u + kkb);
            #pragma unroll
            for (int mf = 0; mf < 4; ++mf)
                #pragma unroll
                for (int jp = 0; jp < 4; ++jp) {
                    mma_tf32(c[mf][2*jp],   a[mf][0], a[mf][1], a[mf][2], a[mf][3],
                             b[jp][0], b[jp][1]);
                    mma_tf32(c[mf][2*jp+1], a[mf][0], a[mf][1], a[mf][2], a[mf][3],
                             b[jp][2], b[jp][3]);
                }
        }
        __syncthreads();

        if (kt + NSTAGE < KTILES) {
            const uint32_t sb = sbase + (uint32_t)(st * STGF) * 4u;
            const int k0 = (kt + NSTAGE) * BK;
            #pragma unroll
            for (int i = 0; i < 8; ++i) {
                const uint32_t ro = (uint32_t)(i * 16 * SA) * 4u;
                cp_async16(sb + sArow + ro, Ag + (size_t)(i * 16) * GK + k0);
                cp_async16(sb + sBrow + ro, Bg + (size_t)(i * 16) * GK + k0);
            }
        }
        CP_ASYNC_COMMIT();
    }

    const int crow = m0 + wm * 64 + lq;
    const int ccol = n0 + wn * 64 + 2 * kq;
    #pragma unroll
    for (int nf = 0; nf < 8; ++nf) {
        const int col = ccol + nf * 8;
        const float2 bb = *(const float2*)(bias + col);
        #pragma unroll
        for (int mf = 0; mf < 4; ++mf) {
            const int row = crow + mf * 16;
            float2 v0, v1;
            v0.x = c[mf][nf][0] + bb.x; v0.y = c[mf][nf][1] + bb.y;
            v1.x = c[mf][nf][2] + bb.x; v1.y = c[mf][nf][3] + bb.y;
            if (round_out) {
                v0.x = f2tf32f(v0.x); v0.y = f2tf32f(v0.y);
                v1.x = f2tf32f(v1.x); v1.y = f2tf32f(v1.y);
            }
            *(float2*)(C + (size_t)row * N + col)       = v0;
            *(float2*)(C + (size_t)(row + 8) * N + col) = v1;
        }
    }
}

// ===========================================================================
// Tensor-core causal flash attention — 4 warps x m32, ldmatrix everywhere,
// V staged transposed, P via quad-shuffle (no P smem slab).
// qkv is already tf32-rounded (GEMM epilogue), so staging has no cvts.
//   Qs: 128 x AQS   Ks: 64 x AQS   Vt: 64 x AQS (d-major)
// ===========================================================================
#define AQS 68
#define ATT_SMEM_BYTES ((128 + 64 + 64) * AQS * 4)   // 69632

__global__ __launch_bounds__(128, 2) void flash_attn_tc(
    const float* __restrict__ qkv, float* __restrict__ out)
{
    extern __shared__ float fsm[];
    float* Qs = fsm;                   // 128 x AQS
    float* Ks = Qs + 128 * AQS;        // 64 x AQS  (n=key j rows, k cols)
    float* Vt = Ks + 64 * AQS;         // 64 x AQS  (n=d rows, k=key j cols)

    const int tid  = threadIdx.x;
    const int wid  = tid >> 5;
    const int lane = tid & 31;
    const int lq   = lane >> 2;
    const int kq   = lane & 3;
    const int qt   = gridDim.x - 1 - blockIdx.x;   // big blocks first
    const int h    = blockIdx.y;
    const int b    = blockIdx.z;
    const int qbase = qt * 128;
    const int qw    = qbase + wid * 32;            // warp's first q row

    const uint32_t sb = smem_u32(fsm);

    // ---- stage Q (x 0.125 exact; data already tf32) ----
    {
        const int r  = tid >> 2;          // 0..31 (+32 per pass)
        const int cg = (tid & 3) * 16;
        #pragma unroll
        for (int p = 0; p < 4; ++p) {
            const int row = r + p * 32;
            const float* src = qkv + ((size_t)b * SEQ + qbase + row) * C3 + h * HD + cg;
            float* dst = Qs + row * AQS + cg;
            #pragma unroll
            for (int i = 0; i < 4; ++i) {
                float4 v = __ldg((const float4*)(src + i * 4));
                v.x *= 0.125f; v.y *= 0.125f; v.z *= 0.125f; v.w *= 0.125f;
                *(float4*)(dst + i * 4) = v;
            }
        }
    }

    // ldmatrix per-lane addresses
    const int xrow = (lane & 7) + ((lane & 8) ? 8 : 0);     // A pattern
    const int xcol = (lane & 16) ? 4 : 0;
    const uint32_t aQ = sb + (uint32_t)((wid * 32 + xrow) * AQS + xcol) * 4u;
    const int yrow = (lane & 7) + ((lane & 16) ? 8 : 0);    // B pattern
    const int ycol = (lane & 8) ? 4 : 0;
    const uint32_t aK = sb + (uint32_t)((128 + yrow) * AQS + ycol) * 4u;
    const uint32_t aV = sb + (uint32_t)((192 + yrow) * AQS + ycol) * 4u;

    float o[2][8][4];
    #pragma unroll
    for (int mi = 0; mi < 2; ++mi)
        #pragma unroll
        for (int nf = 0; nf < 8; ++nf)
            #pragma unroll
            for (int j = 0; j < 4; ++j) o[mi][nf][j] = 0.f;
    float m[4] = {-1e30f, -1e30f, -1e30f, -1e30f};
    float l[4] = {0.f, 0.f, 0.f, 0.f};

    const int sl0 = lq * 4 + (kq >> 1);
    const int sl2 = sl0 + 2;
    const int ntiles = (qt + 1) * 2;

    for (int t = 0; t < ntiles; ++t) {
        const int j0 = t * 64;
        __syncthreads();
        // ---- stage K via cp.async (no transform needed) ----
        {
            const int r  = tid >> 2;
            const int cg = (tid & 3) * 16;
            #pragma unroll
            for (int p = 0; p < 2; ++p) {
                const int row = r + p * 32;
                const float* src = qkv + ((size_t)b * SEQ + j0 + row) * C3 + CH + h * HD + cg;
                const uint32_t dst = sb + (uint32_t)((128 + row) * AQS + cg) * 4u;
                #pragma unroll
                for (int i = 0; i < 4; ++i)
                    cp_async16(dst + i * 16u, src + i * 4);
            }
            CP_ASYNC_COMMIT();
        }
        // ---- stage V transposed: Vt[d][j] ----
        {
            #pragma unroll
            for (int jh = 0; jh < 2; ++jh) {
                const int j = lane + jh * 32;
                const float* vb = qkv + ((size_t)b * SEQ + j0 + j) * C3 + 2 * CH + h * HD + wid * 16;
                #pragma unroll
                for (int c4 = 0; c4 < 4; ++c4) {
                    float4 v = __ldg((const float4*)(vb + c4 * 4));
                    const int d0 = wid * 16 + c4 * 4;
                    Vt[(d0 + 0) * AQS + j] = v.x;
                    Vt[(d0 + 1) * AQS + j] = v.y;
                    Vt[(d0 + 2) * AQS + j] = v.z;
                    Vt[(d0 + 3) * AQS + j] = v.w;
                }
            }
        }
        CP_ASYNC_WAIT(0);
        __syncthreads();

        if (j0 > qw + 31) continue;   // warp fully above diagonal

        // ---- S = Q @ K^T ----
        float s[2][8][4];
        #pragma unroll
        for (int mi = 0; mi < 2; ++mi)
            #pragma unroll
            for (int nf = 0; nf < 8; ++nf)
                #pragma unroll
                for (int j = 0; j < 4; ++j) s[mi][nf][j] = 0.f;

        #pragma unroll
        for (int kc = 0; kc < 8; ++kc) {
            const uint32_t kkb = (uint32_t)kc * 32u;
            uint32_t aq[2][4], bk[4][4];
            ldsm4(aq[0], aQ + kkb);
            ldsm4(aq[1], aQ + (uint32_t)(16 * AQS) * 4u + kkb);
            #pragma unroll
            for (int jp = 0; jp < 4; ++jp)
                ldsm4(bk[jp], aK + (uint32_t)(jp * 16 * AQS) * 4u + kkb);
            #pragma unroll
            for (int mi = 0; mi < 2; ++mi)
                #pragma unroll
                for (int jp = 0; jp < 4; ++jp) {
                    mma_tf32(s[mi][2*jp],   aq[mi][0], aq[mi][1], aq[mi][2], aq[mi][3],
                             bk[jp][0], bk[jp][1]);
                    mma_tf32(s[mi][2*jp+1], aq[mi][0], aq[mi][1], aq[mi][2], aq[mi][3],
                             bk[jp][2], bk[jp][3]);
                }
        }

        // ---- causal mask ----
        if (j0 + 63 > qw) {
            #pragma unroll
            for (int mi = 0; mi < 2; ++mi) {
                const int r0 = qw + mi * 16 + lq, r1 = r0 + 8;
                #pragma unroll
                for (int nf = 0; nf < 8; ++nf) {
                    const int col = j0 + nf * 8 + 2 * kq;
                    if (col     > r0) s[mi][nf][0] = -1e30f;
                    if (col + 1 > r0) s[mi][nf][1] = -1e30f;
                    if (col     > r1) s[mi][nf][2] = -1e30f;
                    if (col + 1 > r1) s[mi][nf][3] = -1e30f;
                }
            }
        }

        // ---- online softmax (per mi, two row groups) ----
        #pragma unroll
        for (int mi = 0; mi < 2; ++mi) {
            float tmA = -1e30f, tmB = -1e30f;
            #pragma unroll
            for (int nf = 0; nf < 8; ++nf) {
                tmA = fmaxf(tmA, fmaxf(s[mi][nf][0], s[mi][nf][1]));
                tmB = fmaxf(tmB, fmaxf(s[mi][nf][2], s[mi][nf][3]));
            }
            tmA = fmaxf(tmA, __shfl_xor_sync(0xffffffffu, tmA, 1));
            tmA = fmaxf(tmA, __shfl_xor_sync(0xffffffffu, tmA, 2));
            tmB = fmaxf(tmB, __shfl_xor_sync(0xffffffffu, tmB, 1));
            tmB = fmaxf(tmB, __shfl_xor_sync(0xffffffffu, tmB, 2));

            const int ia = mi * 2, ib = mi * 2 + 1;
            const float nmA = fmaxf(m[ia], tmA);
            const float nmB = fmaxf(m[ib], tmB);
            const float corrA = __expf(m[ia] - nmA);
            const float corrB = __expf(m[ib] - nmB);
            m[ia] = nmA; m[ib] = nmB;

            float sumA = 0.f, sumB = 0.f;
            #pragma unroll
            for (int nf = 0; nf < 8; ++nf) {
                const float p0 = __expf(s[mi][nf][0] - nmA);
                const float p1 = __expf(s[mi][nf][1] - nmA);
                const float p2 = __expf(s[mi][nf][2] - nmB);
                const float p3 = __expf(s[mi][nf][3] - nmB);
                sumA += p0 + p1;
                sumB += p2 + p3;
                s[mi][nf][0] = f2tf32f(p0);
                s[mi][nf][1] = f2tf32f(p1);
                s[mi][nf][2] = f2tf32f(p2);
                s[mi][nf][3] = f2tf32f(p3);
            }
            sumA += __shfl_xor_sync(0xffffffffu, sumA, 1);
            sumA += __shfl_xor_sync(0xffffffffu, sumA, 2);
            sumB += __shfl_xor_sync(0xffffffffu, sumB, 1);
            sumB += __shfl_xor_sync(0xffffffffu, sumB, 2);
            l[ia] = l[ia] * corrA + sumA;
            l[ib] = l[ib] * corrB + sumB;

            #pragma unroll
            for (int nf = 0; nf < 8; ++nf) {
                o[mi][nf][0] *= corrA; o[mi][nf][1] *= corrA;
                o[mi][nf][2] *= corrB; o[mi][nf][3] *= corrB;
            }
        }

        // ---- O += P @ V  (P fragment via quad shuffles; V via ldmatrix) ----
        #pragma unroll
        for (int kc = 0; kc < 8; ++kc) {
            const uint32_t kkb = (uint32_t)kc * 32u;
            uint32_t bv[4][4];
            #pragma unroll
            for (int jp = 0; jp < 4; ++jp)
                ldsm4(bv[jp], aV + (uint32_t)(jp * 16 * AQS) * 4u + kkb);
            #pragma unroll
            for (int mi = 0; mi < 2; ++mi) {
                const float p0 = s[mi][kc][0], p1 = s[mi][kc][1];
                const float p2 = s[mi][kc][2], p3 = s[mi][kc][3];
                const float e00 = __shfl_sync(0xffffffffu, p0, sl0);
                const float e01 = __shfl_sync(0xffffffffu, p1, sl0);
                const float e10 = __shfl_sync(0xffffffffu, p2, sl0);
                const float e11 = __shfl_sync(0xffffffffu, p3, sl0);
                const float f00 = __shfl_sync(0xffffffffu, p0, sl2);
                const float f01 = __shfl_sync(0xffffffffu, p1, sl2);
                const float f10 = __shfl_sync(0xffffffffu, p2, sl2);
                const float f11 = __shfl_sync(0xffffffffu, p3, sl2);
                const uint32_t a0 = __float_as_uint((kq & 1) ? e01 : e00);
                const uint32_t a1 = __float_as_uint((kq & 1) ? e11 : e10);
                const uint32_t a2 = __float_as_uint((kq & 1) ? f01 : f00);
                const uint32_t a3 = __float_as_uint((kq & 1) ? f11 : f10);
                #pragma unroll
                for (int jp = 0; jp < 4; ++jp) {
                    mma_tf32(o[mi][2*jp],   a0, a1, a2, a3, bv[jp][0], bv[jp][1]);
                    mma_tf32(o[mi][2*jp+1], a0, a1, a2, a3, bv[jp][2], bv[jp][3]);
                }
            }
        }
    }

    // ---- epilogue (tf32-rounded: proj GEMM consumes it cvt-free) ----
    #pragma unroll
    for (int mi = 0; mi < 2; ++mi) {
        const float invA = 1.f / l[mi * 2];
        const float invB = 1.f / l[mi * 2 + 1];
        const int row0 = qw + mi * 16 + lq;
        float* op0 = out + ((size_t)b * SEQ + row0) * CH + h * HD;
        float* op1 = op0 + (size_t)8 * CH;
        #pragma unroll
        for (int nf = 0; nf < 8; ++nf) {
            const int cc = nf * 8 + 2 * kq;
            float2 v0, v1;
            v0.x = f2tf32f(o[mi][nf][0] * invA); v0.y = f2tf32f(o[mi][nf][1] * invA);
            v1.x = f2tf32f(o[mi][nf][2] * invB); v1.y = f2tf32f(o[mi][nf][3] * invB);
            *(float2*)(op0 + cc) = v0;
            *(float2*)(op1 + cc) = v1;
        }
    }
}

// ---------------------------------------------------------------------------
extern "C" void kernel_launch(void* const* d_in, const int* in_sizes, int n_in,
                              void* d_out, int out_size)
{
    const float* x      = (const float*)d_in[0];
    const float* W_attn = (const float*)d_in[1];
    const float* b_attn = (const float*)d_in[2];
    const float* W_proj = (const float*)d_in[3];
    const float* b_proj = (const float*)d_in[4];
    float* out = (float*)d_out;

    float* qkv; cudaGetSymbolAddress((void**)&qkv, g_qkv);
    float* att; cudaGetSymbolAddress((void**)&att, g_att);
    float* xs;  cudaGetSymbolAddress((void**)&xs,  g_xs);
    float* was; cudaGetSymbolAddress((void**)&was, g_was);
    float* wps; cudaGetSymbolAddress((void**)&wps, g_wps);

    cudaFuncSetAttribute(gemm_mma_tf32,
                         cudaFuncAttributeMaxDynamicSharedMemorySize, GEMM_SMEM_BYTES);
    cudaFuncSetAttribute(flash_attn_tc,
                         cudaFuncAttributeMaxDynamicSharedMemorySize, ATT_SMEM_BYTES);

    const int M = BATCH * SEQ;  // 8192

    // 0) pre-round GEMM operands to tf32
    {
        const int nx = M * CH / 4, na = C3 * CH / 4, np = CH * CH / 4;
        cvt_tf32_kernel<<<(nx + 255) / 256, 256>>>((const float4*)x,      (float4*)xs,  nx);
        cvt_tf32_kernel<<<(na + 255) / 256, 256>>>((const float4*)W_attn, (float4*)was, na);
        cvt_tf32_kernel<<<(np + 255) / 256, 256>>>((const float4*)W_proj, (float4*)wps, np);
    }
    // 1) QKV projection (output tf32-rounded for attention staging)
    {
        dim3 grid(C3 / BN, M / BM);
        gemm_mma_tf32<<<grid, 128, GEMM_SMEM_BYTES>>>(xs, was, b_attn, qkv, M, C3, 1);
    }
    // 2) causal flash attention
    {
        dim3 grid(SEQ / 128, NHEAD, BATCH);
        flash_attn_tc<<<grid, 128, ATT_SMEM_BYTES>>>(qkv, att);
    }
    // 3) output projection (final output, NOT rounded)
    {
        dim3 grid(CH / BN, M / BM);
        gemm_mma_tf32<<<grid, 128, GEMM_SMEM_BYTES>>>(att, wps, b_proj, out, M, CH, 0);
    }
}

// round 8
// speedup vs baseline: 4.1335x; 1.0306x over previous
#include <cuda_runtime.h>
#include <cstdint>

// Problem constants
#define BATCH 4
#define SEQ   2048
#define CH    1024
#define NHEAD 16
#define HD    64
#define C3    (3*CH)

// Scratch (no cudaMalloc allowed)
__device__ float g_qkv[(size_t)BATCH * SEQ * C3];   // 96 MB (tf32-rounded by GEMM)
__device__ float g_att[(size_t)BATCH * SEQ * CH];   // 32 MB (tf32-rounded)
__device__ float g_xs [(size_t)BATCH * SEQ * CH];   // 32 MB  x tf32
__device__ float g_was[(size_t)C3 * CH];            // 12 MB  W_attn tf32
__device__ float g_wps[(size_t)CH * CH];            //  4 MB  W_proj tf32
__device__ float g_vt [(size_t)BATCH * NHEAD * HD * SEQ];  // 32 MB  V transposed [b,h,d,t]

// ===========================================================================
// Common helpers
// ===========================================================================
__device__ __forceinline__ uint32_t smem_u32(const void* p) {
    uint32_t a;
    asm("{ .reg .u64 t; cvta.to.shared.u64 t, %1; cvt.u32.u64 %0, t; }" : "=r"(a) : "l"(p));
    return a;
}

__device__ __forceinline__ void cp_async16(uint32_t smem_addr, const void* gptr) {
    asm volatile("cp.async.cg.shared.global [%0], [%1], 16;" :: "r"(smem_addr), "l"(gptr));
}
#define CP_ASYNC_COMMIT() asm volatile("cp.async.commit_group;" ::: "memory")
#define CP_ASYNC_WAIT(n)  asm volatile("cp.async.wait_group %0;" :: "n"(n) : "memory")

__device__ __forceinline__ uint32_t f2tf32(float f) {
    uint32_t r;
    asm("cvt.rna.tf32.f32 %0, %1;" : "=r"(r) : "f"(f));
    return r;
}
__device__ __forceinline__ float f2tf32f(float f) {
    return __uint_as_float(f2tf32(f));
}

__device__ __forceinline__ void mma_tf32(float* c,
    uint32_t a0, uint32_t a1, uint32_t a2, uint32_t a3, uint32_t b0, uint32_t b1)
{
    asm volatile(
        "mma.sync.aligned.m16n8k8.row.col.f32.tf32.tf32.f32 "
        "{%0,%1,%2,%3}, {%4,%5,%6,%7}, {%8,%9}, {%0,%1,%2,%3};"
        : "+f"(c[0]), "+f"(c[1]), "+f"(c[2]), "+f"(c[3])
        : "r"(a0), "r"(a1), "r"(a2), "r"(a3), "r"(b0), "r"(b1));
}

// ldmatrix x4 (b16 tiles; tf32 data: each 8x8xb16 tile == 8x4xtf32 tile)
__device__ __forceinline__ void ldsm4(uint32_t* r, uint32_t addr) {
    asm volatile("ldmatrix.sync.aligned.m8n8.x4.shared.b16 {%0,%1,%2,%3}, [%4];"
        : "=r"(r[0]), "=r"(r[1]), "=r"(r[2]), "=r"(r[3]) : "r"(addr));
}

// ===========================================================================
// Elementwise tf32 pre-round
// ===========================================================================
__global__ __launch_bounds__(256) void cvt_tf32_kernel(
    const float4* __restrict__ in, float4* __restrict__ out, int n4)
{
    const int i = blockIdx.x * blockDim.x + threadIdx.x;
    if (i < n4) {
        float4 v = in[i];
        v.x = f2tf32f(v.x); v.y = f2tf32f(v.y);
        v.z = f2tf32f(v.z); v.w = f2tf32f(v.w);
        out[i] = v;
    }
}

// ===========================================================================
// V transpose: qkv[b, t, 2C + h*64 + d] -> vt[((b*16+h)*64 + d)*SEQ + t]
// 64x64 tiles via smem (64x65). Pure bit-copy (data already tf32).
// ===========================================================================
__global__ __launch_bounds__(256) void transpose_v(
    const float* __restrict__ qkv, float* __restrict__ vt)
{
    __shared__ float ts[64][65];
    const int t0 = blockIdx.x * 64;
    const int h  = blockIdx.y;
    const int b  = blockIdx.z;
    const int tid = threadIdx.x;

    // load: row = t offset, cols = d
    {
        const int r  = tid >> 2;          // 0..63
        const int cg = (tid & 3) * 16;    // 0,16,32,48
        const float* src = qkv + ((size_t)b * SEQ + t0 + r) * C3 + 2 * CH + h * HD + cg;
        #pragma unroll
        for (int i = 0; i < 4; ++i) {
            float4 v = __ldg((const float4*)(src + i * 4));
            ts[r][cg + i * 4 + 0] = v.x;
            ts[r][cg + i * 4 + 1] = v.y;
            ts[r][cg + i * 4 + 2] = v.z;
            ts[r][cg + i * 4 + 3] = v.w;
        }
    }
    __syncthreads();
    // store: thread (d = tid>>2, q = tid&3) writes t0 + q*16 .. +15
    {
        const int d = tid >> 2;
        const int q = (tid & 3) * 16;
        float* dst = vt + (((size_t)b * NHEAD + h) * HD + d) * SEQ + t0 + q;
        #pragma unroll
        for (int i = 0; i < 4; ++i) {
            float4 v;
            v.x = ts[q + i * 4 + 0][d];
            v.y = ts[q + i * 4 + 1][d];
            v.z = ts[q + i * 4 + 2][d];
            v.w = ts[q + i * 4 + 3][d];
            *(float4*)(dst + i * 4) = v;
        }
    }
}

// ===========================================================================
// mma.sync tf32 GEMM (unchanged from R7)
// ===========================================================================
#define GK   1024
#define BM   128
#define BN   128
#define BK   32
#define KTILES (GK/BK)
#define SA   36
#define ASTG (BM*SA)
#define STGF (2*ASTG)
#define NSTAGE 3
#define GEMM_SMEM_BYTES (NSTAGE*STGF*4)

__global__ __launch_bounds__(128, 2) void gemm_mma_tf32(
    const float* __restrict__ A, const float* __restrict__ B,
    const float* __restrict__ bias, float* __restrict__ C,
    int M, int N, int round_out)
{
    extern __shared__ float smem[];
    const uint32_t sbase = smem_u32(smem);

    const int tid  = threadIdx.x;
    const int wid  = tid >> 5;
    const int lane = tid & 31;
    const int wm   = wid & 1;
    const int wn   = wid >> 1;
    const int lq   = lane >> 2;
    const int kq   = lane & 3;
    const int m0 = blockIdx.y * BM;
    const int n0 = blockIdx.x * BN;

    const int lrow = tid >> 3;
    const int lc   = (tid & 7) * 4;
    const float* Ag = A + (size_t)(m0 + lrow) * GK + lc;
    const float* Bg = B + (size_t)(n0 + lrow) * GK + lc;
    const uint32_t sArow = (uint32_t)(lrow * SA + lc) * 4u;
    const uint32_t sBrow = (uint32_t)(ASTG + lrow * SA + lc) * 4u;

    const int arow = wm * 64 + (lane & 7) + ((lane & 8) ? 8 : 0);
    const int acol = (lane & 16) ? 4 : 0;
    const uint32_t aoff = (uint32_t)(arow * SA + acol) * 4u;
    const int brow = wn * 64 + (lane & 7) + ((lane & 16) ? 8 : 0);
    const int bcol = (lane & 8) ? 4 : 0;
    const uint32_t boff = (uint32_t)(ASTG + brow * SA + bcol) * 4u;

    float c[4][8][4];
    #pragma unroll
    for (int i = 0; i < 4; ++i)
        #pragma unroll
        for (int j = 0; j < 8; ++j)
            #pragma unroll
            for (int r = 0; r < 4; ++r) c[i][j][r] = 0.f;

    #pragma unroll
    for (int s = 0; s < NSTAGE; ++s) {
        const uint32_t sb = sbase + (uint32_t)(s * STGF) * 4u;
        const int k0 = s * BK;
        #pragma unroll
        for (int i = 0; i < 8; ++i) {
            const uint32_t ro = (uint32_t)(i * 16 * SA) * 4u;
            cp_async16(sb + sArow + ro, Ag + (size_t)(i * 16) * GK + k0);
            cp_async16(sb + sBrow + ro, Bg + (size_t)(i * 16) * GK + k0);
        }
        CP_ASYNC_COMMIT();
    }

    for (int kt = 0; kt < KTILES; ++kt) {
        CP_ASYNC_WAIT(2);
        __syncthreads();

        const int st = kt % NSTAGE;
        const uint32_t Ab = sbase + (uint32_t)(st * STGF) * 4u + aoff;
        const uint32_t Bb = sbase + (uint32_t)(st * STGF) * 4u + boff;

        #pragma unroll
        for (int ks = 0; ks < 4; ++ks) {
            const uint32_t kkb = (uint32_t)(ks * 8) * 4u;
            uint32_t a[4][4], b[4][4];
            #pragma unroll
            for (int mf = 0; mf < 4; ++mf)
                ldsm4(a[mf], Ab + (uint32_t)(mf * 16 * SA) * 4u + kkb);
            #pragma unroll
            for (int jp = 0; jp < 4; ++jp)
                ldsm4(b[jp], Bb + (uint32_t)(jp * 16 * SA) * 4u + kkb);
            #pragma unroll
            for (int mf = 0; mf < 4; ++mf)
                #pragma unroll
                for (int jp = 0; jp < 4; ++jp) {
                    mma_tf32(c[mf][2*jp],   a[mf][0], a[mf][1], a[mf][2], a[mf][3],
                             b[jp][0], b[jp][1]);
                    mma_tf32(c[mf][2*jp+1], a[mf][0], a[mf][1], a[mf][2], a[mf][3],
                             b[jp][2], b[jp][3]);
                }
        }
        __syncthreads();

        if (kt + NSTAGE < KTILES) {
            const uint32_t sb = sbase + (uint32_t)(st * STGF) * 4u;
            const int k0 = (kt + NSTAGE) * BK;
            #pragma unroll
            for (int i = 0; i < 8; ++i) {
                const uint32_t ro = (uint32_t)(i * 16 * SA) * 4u;
                cp_async16(sb + sArow + ro, Ag + (size_t)(i * 16) * GK + k0);
                cp_async16(sb + sBrow + ro, Bg + (size_t)(i * 16) * GK + k0);
            }
        }
        CP_ASYNC_COMMIT();
    }

    const int crow = m0 + wm * 64 + lq;
    const int ccol = n0 + wn * 64 + 2 * kq;
    #pragma unroll
    for (int nf = 0; nf < 8; ++nf) {
        const int col = ccol + nf * 8;
        const float2 bb = *(const float2*)(bias + col);
        #pragma unroll
        for (int mf = 0; mf < 4; ++mf) {
            const int row = crow + mf * 16;
            float2 v0, v1;
            v0.x = c[mf][nf][0] + bb.x; v0.y = c[mf][nf][1] + bb.y;
            v1.x = c[mf][nf][2] + bb.x; v1.y = c[mf][nf][3] + bb.y;
            if (round_out) {
                v0.x = f2tf32f(v0.x); v0.y = f2tf32f(v0.y);
                v1.x = f2tf32f(v1.x); v1.y = f2tf32f(v1.y);
            }
            *(float2*)(C + (size_t)row * N + col)       = v0;
            *(float2*)(C + (size_t)(row + 8) * N + col) = v1;
        }
    }
}

// ===========================================================================
// Tensor-core causal flash attention — 4 warps x m32, double-buffered
// cp.async K/Vt staging (V pre-transposed globally), P via quad-shuffle.
// SMEM rows (stride AQS): Q 0-127, K0 128-191, K1 192-255, V0 256-319, V1 320-383
// ===========================================================================
#define AQS 68
#define ATT_SMEM_BYTES (384 * AQS * 4)   // 104448

__global__ __launch_bounds__(128, 2) void flash_attn_tc(
    const float* __restrict__ qkv, const float* __restrict__ vt,
    float* __restrict__ out)
{
    extern __shared__ float fsm[];
    float* Qs = fsm;

    const int tid  = threadIdx.x;
    const int wid  = tid >> 5;
    const int lane = tid & 31;
    const int lq   = lane >> 2;
    const int kq   = lane & 3;
    const int qt   = gridDim.x - 1 - blockIdx.x;   // big blocks first
    const int h    = blockIdx.y;
    const int b    = blockIdx.z;
    const int qbase = qt * 128;
    const int qw    = qbase + wid * 32;

    const uint32_t sb = smem_u32(fsm);
    const float* vtb = vt + ((size_t)b * NHEAD + h) * HD * SEQ;

    // staging thread mapping (shared by K and Vt)
    const int sr = tid >> 2;          // 0..31 (+32 per pass)
    const int scg = (tid & 3) * 16;   // 0,16,32,48

    // ---- prologue: issue tile 0 into buf 0 ----
    {
        #pragma unroll
        for (int p = 0; p < 2; ++p) {
            const int row = sr + p * 32;
            const float* ksrc = qkv + ((size_t)b * SEQ + row) * C3 + CH + h * HD + scg;
            const uint32_t kdst = sb + (uint32_t)((128 + row) * AQS + scg) * 4u;
            const float* vsrc = vtb + (size_t)row * SEQ + scg;
            const uint32_t vdst = sb + (uint32_t)((256 + row) * AQS + scg) * 4u;
            #pragma unroll
            for (int i = 0; i < 4; ++i) {
                cp_async16(kdst + i * 16u, ksrc + i * 4);
                cp_async16(vdst + i * 16u, vsrc + i * 4);
            }
        }
        CP_ASYNC_COMMIT();
    }

    // ---- stage Q (x 0.125 exact; data already tf32) ----
    {
        #pragma unroll
        for (int p = 0; p < 4; ++p) {
            const int row = sr + p * 32;
            const float* src = qkv + ((size_t)b * SEQ + qbase + row) * C3 + h * HD + scg;
            float* dst = Qs + row * AQS + scg;
            #pragma unroll
            for (int i = 0; i < 4; ++i) {
                float4 v = __ldg((const float4*)(src + i * 4));
                v.x *= 0.125f; v.y *= 0.125f; v.z *= 0.125f; v.w *= 0.125f;
                *(float4*)(dst + i * 4) = v;
            }
        }
    }

    // ldmatrix per-lane addresses
    const int xrow = (lane & 7) + ((lane & 8) ? 8 : 0);     // A pattern
    const int xcol = (lane & 16) ? 4 : 0;
    const uint32_t aQ = sb + (uint32_t)((wid * 32 + xrow) * AQS + xcol) * 4u;
    const int yrow = (lane & 7) + ((lane & 16) ? 8 : 0);    // B pattern
    const int ycol = (lane & 8) ? 4 : 0;
    const uint32_t aK0 = sb + (uint32_t)((128 + yrow) * AQS + ycol) * 4u;
    const uint32_t aV0 = sb + (uint32_t)((256 + yrow) * AQS + ycol) * 4u;
    const uint32_t BUFB = (uint32_t)(64 * AQS) * 4u;

    float o[2][8][4];
    #pragma unroll
    for (int mi = 0; mi < 2; ++mi)
        #pragma unroll
        for (int nf = 0; nf < 8; ++nf)
            #pragma unroll
            for (int j = 0; j < 4; ++j) o[mi][nf][j] = 0.f;
    float m[4] = {-1e30f, -1e30f, -1e30f, -1e30f};
    float l[4] = {0.f, 0.f, 0.f, 0.f};

    const int sl0 = lq * 4 + (kq >> 1);
    const int sl2 = sl0 + 2;
    const int ntiles = (qt + 1) * 2;

    for (int t = 0; t < ntiles; ++t) {
        // issue next tile, then wait for current
        if (t + 1 < ntiles) {
            const int j1 = (t + 1) * 64;
            const uint32_t bo = ((t + 1) & 1) ? BUFB : 0u;
            #pragma unroll
            for (int p = 0; p < 2; ++p) {
                const int row = sr + p * 32;
                const float* ksrc = qkv + ((size_t)b * SEQ + j1 + row) * C3 + CH + h * HD + scg;
                const uint32_t kdst = sb + (uint32_t)((128 + row) * AQS + scg) * 4u + bo;
                const float* vsrc = vtb + (size_t)row * SEQ + j1 + scg;
                const uint32_t vdst = sb + (uint32_t)((256 + row) * AQS + scg) * 4u + bo;
                #pragma unroll
                for (int i = 0; i < 4; ++i) {
                    cp_async16(kdst + i * 16u, ksrc + i * 4);
                    cp_async16(vdst + i * 16u, vsrc + i * 4);
                }
            }
            CP_ASYNC_COMMIT();
            CP_ASYNC_WAIT(1);
        } else {
            CP_ASYNC_WAIT(0);
        }
        __syncthreads();

        const int j0 = t * 64;
        if (j0 <= qw + 31) {
            const uint32_t bo = (t & 1) ? BUFB : 0u;
            const uint32_t aK = aK0 + bo;
            const uint32_t aV = aV0 + bo;

            // ---- S = Q @ K^T ----
            float s[2][8][4];
            #pragma unroll
            for (int mi = 0; mi < 2; ++mi)
                #pragma unroll
                for (int nf = 0; nf < 8; ++nf)
                    #pragma unroll
                    for (int j = 0; j < 4; ++j) s[mi][nf][j] = 0.f;

            #pragma unroll
            for (int kc = 0; kc < 8; ++kc) {
                const uint32_t kkb = (uint32_t)kc * 32u;
                uint32_t aq[2][4], bk[4][4];
                ldsm4(aq[0], aQ + kkb);
                ldsm4(aq[1], aQ + (uint32_t)(16 * AQS) * 4u + kkb);
                #pragma unroll
                for (int jp = 0; jp < 4; ++jp)
                    ldsm4(bk[jp], aK + (uint32_t)(jp * 16 * AQS) * 4u + kkb);
                #pragma unroll
                for (int mi = 0; mi < 2; ++mi)
                    #pragma unroll
                    for (int jp = 0; jp < 4; ++jp) {
                        mma_tf32(s[mi][2*jp],   aq[mi][0], aq[mi][1], aq[mi][2], aq[mi][3],
                                 bk[jp][0], bk[jp][1]);
                        mma_tf32(s[mi][2*jp+1], aq[mi][0], aq[mi][1], aq[mi][2], aq[mi][3],
                                 bk[jp][2], bk[jp][3]);
                    }
            }

            // ---- causal mask ----
            if (j0 + 63 > qw) {
                #pragma unroll
                for (int mi = 0; mi < 2; ++mi) {
                    const int r0 = qw + mi * 16 + lq, r1 = r0 + 8;
                    #pragma unroll
                    for (int nf = 0; nf < 8; ++nf) {
                        const int col = j0 + nf * 8 + 2 * kq;
                        if (col     > r0) s[mi][nf][0] = -1e30f;
                        if (col + 1 > r0) s[mi][nf][1] = -1e30f;
                        if (col     > r1) s[mi][nf][2] = -1e30f;
                        if (col + 1 > r1) s[mi][nf][3] = -1e30f;
                    }
                }
            }

            // ---- online softmax ----
            #pragma unroll
            for (int mi = 0; mi < 2; ++mi) {
                float tmA = -1e30f, tmB = -1e30f;
                #pragma unroll
                for (int nf = 0; nf < 8; ++nf) {
                    tmA = fmaxf(tmA, fmaxf(s[mi][nf][0], s[mi][nf][1]));
                    tmB = fmaxf(tmB, fmaxf(s[mi][nf][2], s[mi][nf][3]));
                }
                tmA = fmaxf(tmA, __shfl_xor_sync(0xffffffffu, tmA, 1));
                tmA = fmaxf(tmA, __shfl_xor_sync(0xffffffffu, tmA, 2));
                tmB = fmaxf(tmB, __shfl_xor_sync(0xffffffffu, tmB, 1));
                tmB = fmaxf(tmB, __shfl_xor_sync(0xffffffffu, tmB, 2));

                const int ia = mi * 2, ib = mi * 2 + 1;
                const float nmA = fmaxf(m[ia], tmA);
                const float nmB = fmaxf(m[ib], tmB);
                const float corrA = __expf(m[ia] - nmA);
                const float corrB = __expf(m[ib] - nmB);
                m[ia] = nmA; m[ib] = nmB;

                float sumA = 0.f, sumB = 0.f;
                #pragma unroll
                for (int nf = 0; nf < 8; ++nf) {
                    const float p0 = __expf(s[mi][nf][0] - nmA);
                    const float p1 = __expf(s[mi][nf][1] - nmA);
                    const float p2 = __expf(s[mi][nf][2] - nmB);
                    const float p3 = __expf(s[mi][nf][3] - nmB);
                    sumA += p0 + p1;
                    sumB += p2 + p3;
                    s[mi][nf][0] = f2tf32f(p0);
                    s[mi][nf][1] = f2tf32f(p1);
                    s[mi][nf][2] = f2tf32f(p2);
                    s[mi][nf][3] = f2tf32f(p3);
                }
                sumA += __shfl_xor_sync(0xffffffffu, sumA, 1);
                sumA += __shfl_xor_sync(0xffffffffu, sumA, 2);
                sumB += __shfl_xor_sync(0xffffffffu, sumB, 1);
                sumB += __shfl_xor_sync(0xffffffffu, sumB, 2);
                l[ia] = l[ia] * corrA + sumA;
                l[ib] = l[ib] * corrB + sumB;

                #pragma unroll
                for (int nf = 0; nf < 8; ++nf) {
                    o[mi][nf][0] *= corrA; o[mi][nf][1] *= corrA;
                    o[mi][nf][2] *= corrB; o[mi][nf][3] *= corrB;
                }
            }

            // ---- O += P @ V ----
            #pragma unroll
            for (int kc = 0; kc < 8; ++kc) {
                const uint32_t kkb = (uint32_t)kc * 32u;
                uint32_t bv[4][4];
                #pragma unroll
                for (int jp = 0; jp < 4; ++jp)
                    ldsm4(bv[jp], aV + (uint32_t)(jp * 16 * AQS) * 4u + kkb);
                #pragma unroll
                for (int mi = 0; mi < 2; ++mi) {
                    const float p0 = s[mi][kc][0], p1 = s[mi][kc][1];
                    const float p2 = s[mi][kc][2], p3 = s[mi][kc][3];
                    const float e00 = __shfl_sync(0xffffffffu, p0, sl0);
                    const float e01 = __shfl_sync(0xffffffffu, p1, sl0);
                    const float e10 = __shfl_sync(0xffffffffu, p2, sl0);
                    const float e11 = __shfl_sync(0xffffffffu, p3, sl0);
                    const float f00 = __shfl_sync(0xffffffffu, p0, sl2);
                    const float f01 = __shfl_sync(0xffffffffu, p1, sl2);
                    const float f10 = __shfl_sync(0xffffffffu, p2, sl2);
                    const float f11 = __shfl_sync(0xffffffffu, p3, sl2);
                    const uint32_t a0 = __float_as_uint((kq & 1) ? e01 : e00);
                    const uint32_t a1 = __float_as_uint((kq & 1) ? e11 : e10);
                    const uint32_t a2 = __float_as_uint((kq & 1) ? f01 : f00);
                    const uint32_t a3 = __float_as_uint((kq & 1) ? f11 : f10);
                    #pragma unroll
                    for (int jp = 0; jp < 4; ++jp) {
                        mma_tf32(o[mi][2*jp],   a0, a1, a2, a3, bv[jp][0], bv[jp][1]);
                        mma_tf32(o[mi][2*jp+1], a0, a1, a2, a3, bv[jp][2], bv[jp][3]);
                    }
                }
            }
        }
        __syncthreads();
    }

    // ---- epilogue (tf32-rounded: proj GEMM consumes it cvt-free) ----
    #pragma unroll
    for (int mi = 0; mi < 2; ++mi) {
        const float invA = 1.f / l[mi * 2];
        const float invB = 1.f / l[mi * 2 + 1];
        const int row0 = qw + mi * 16 + lq;
        float* op0 = out + ((size_t)b * SEQ + row0) * CH + h * HD;
        float* op1 = op0 + (size_t)8 * CH;
        #pragma unroll
        for (int nf = 0; nf < 8; ++nf) {
            const int cc = nf * 8 + 2 * kq;
            float2 v0, v1;
            v0.x = f2tf32f(o[mi][nf][0] * invA); v0.y = f2tf32f(o[mi][nf][1] * invA);
            v1.x = f2tf32f(o[mi][nf][2] * invB); v1.y = f2tf32f(o[mi][nf][3] * invB);
            *(float2*)(op0 + cc) = v0;
            *(float2*)(op1 + cc) = v1;
        }
    }
}

// ---------------------------------------------------------------------------
extern "C" void kernel_launch(void* const* d_in, const int* in_sizes, int n_in,
                              void* d_out, int out_size)
{
    const float* x      = (const float*)d_in[0];
    const float* W_attn = (const float*)d_in[1];
    const float* b_attn = (const float*)d_in[2];
    const float* W_proj = (const float*)d_in[3];
    const float* b_proj = (const float*)d_in[4];
    float* out = (float*)d_out;

    float* qkv; cudaGetSymbolAddress((void**)&qkv, g_qkv);
    float* att; cudaGetSymbolAddress((void**)&att, g_att);
    float* xs;  cudaGetSymbolAddress((void**)&xs,  g_xs);
    float* was; cudaGetSymbolAddress((void**)&was, g_was);
    float* wps; cudaGetSymbolAddress((void**)&wps, g_wps);
    float* vt;  cudaGetSymbolAddress((void**)&vt,  g_vt);

    cudaFuncSetAttribute(gemm_mma_tf32,
                         cudaFuncAttributeMaxDynamicSharedMemorySize, GEMM_SMEM_BYTES);
    cudaFuncSetAttribute(flash_attn_tc,
                         cudaFuncAttributeMaxDynamicSharedMemorySize, ATT_SMEM_BYTES);

    const int M = BATCH * SEQ;  // 8192

    // 0) pre-round GEMM operands to tf32
    {
        const int nx = M * CH / 4, na = C3 * CH / 4, np = CH * CH / 4;
        cvt_tf32_kernel<<<(nx + 255) / 256, 256>>>((const float4*)x,      (float4*)xs,  nx);
        cvt_tf32_kernel<<<(na + 255) / 256, 256>>>((const float4*)W_attn, (float4*)was, na);
        cvt_tf32_kernel<<<(np + 255) / 256, 256>>>((const float4*)W_proj, (float4*)wps, np);
    }
    // 1) QKV projection (output tf32-rounded)
    {
        dim3 grid(C3 / BN, M / BM);
        gemm_mma_tf32<<<grid, 128, GEMM_SMEM_BYTES>>>(xs, was, b_attn, qkv, M, C3, 1);
    }
    // 1b) transpose V for attention
    {
        dim3 grid(SEQ / 64, NHEAD, BATCH);
        transpose_v<<<grid, 256>>>(qkv, vt);
    }
    // 2) causal flash attention
    {
        dim3 grid(SEQ / 128, NHEAD, BATCH);
        flash_attn_tc<<<grid, 128, ATT_SMEM_BYTES>>>(qkv, vt, att);
    }
    // 3) output projection (final output, NOT rounded)
    {
        dim3 grid(CH / BN, M / BM);
        gemm_mma_tf32<<<grid, 128, GEMM_SMEM_BYTES>>>(att, wps, b_proj, out, M, CH, 0);
    }
}